// round 12
// baseline (speedup 1.0000x reference)
#include <cuda_runtime.h>
#include <math.h>

#define BB 128
#define SS 256
#define HH 512

typedef unsigned long long u64;

// ---------------- device scratch (no allocations allowed) -------------------
__device__ float g_rsWr[HH];            // rowsum(Wr)
__device__ float g_rsW[HH];             // rowsum(W)
__device__ float g_part[4][BB * SS];    // per-jblock logit partials
__device__ float g_Gt[SS * BB];         // softmax gates, (s, b)
__device__ float g_C[2][HH * BB];       // recurrent state, transposed (h, b)
__device__ unsigned g_flags[8][32];     // per-bg step counters, 128B padded

// ---------------- f32x2 / misc helpers ----------------------------------------
__device__ __forceinline__ u64 pk2(float x, float y) {
    u64 r;
    asm("mov.b64 %0, {%1,%2};" : "=l"(r) : "f"(x), "f"(y));
    return r;
}
__device__ __forceinline__ void upk2(u64 v, float& x, float& y) {
    asm("mov.b64 {%0,%1}, %2;" : "=f"(x), "=f"(y) : "l"(v));
}
__device__ __forceinline__ u64 fma2_(u64 a, u64 b, u64 c) {
    u64 d;
    asm("fma.rn.f32x2 %0, %1, %2, %3;" : "=l"(d) : "l"(a), "l"(b), "l"(c));
    return d;
}
__device__ __forceinline__ u64 add2_(u64 a, u64 b) {
    u64 d;
    asm("add.rn.f32x2 %0, %1, %2;" : "=l"(d) : "l"(a), "l"(b));
    return d;
}
__device__ __forceinline__ float tanh_approx(float x) {
    float y;
    asm("tanh.approx.f32 %0, %1;" : "=f"(y) : "f"(x));
    return y;
}
__device__ __forceinline__ float to_tf32(float x) {
    float y;
    asm("cvt.rna.tf32.f32 %0, %1;" : "=f"(y) : "f"(x));
    return y;
}
__device__ __forceinline__ unsigned ld_acq(const unsigned* p) {
    unsigned v;
    asm volatile("ld.acquire.gpu.global.u32 %0, [%1];" : "=r"(v) : "l"(p));
    return v;
}
__device__ __forceinline__ void red_add_rel(unsigned* p, unsigned v) {
    asm volatile("red.add.release.gpu.global.u32 [%0], %1;" :: "l"(p), "r"(v) : "memory");
}
__device__ __forceinline__ void mma_tf32(float* d, const unsigned* a,
                                         unsigned b0, unsigned b1) {
    asm volatile(
        "mma.sync.aligned.m16n8k8.row.col.f32.tf32.tf32.f32 "
        "{%0,%1,%2,%3}, {%4,%5,%6,%7}, {%8,%9}, {%0,%1,%2,%3};"
        : "+f"(d[0]), "+f"(d[1]), "+f"(d[2]), "+f"(d[3])
        : "r"(a[0]), "r"(a[1]), "r"(a[2]), "r"(a[3]), "r"(b0), "r"(b1));
}

// ---------------- prep: rowsums of Wr and W ----------------------------------
__global__ void prep_kernel(const float* __restrict__ Wr, const float* __restrict__ W)
{
    int warp = threadIdx.x >> 5, lane = threadIdx.x & 31;
    int rowId = blockIdx.x * 8 + warp;               // 0..1023
    const float* src = (rowId < HH) ? Wr : W;
    int h = rowId & (HH - 1);
    const float4* s4 = reinterpret_cast<const float4*>(src + (size_t)h * HH);
    float s = 0.f;
    for (int i = lane; i < HH / 4; i += 32) {
        float4 v = s4[i];
        s += (v.x + v.y) + (v.z + v.w);
    }
#pragma unroll
    for (int o = 16; o > 0; o >>= 1) s += __shfl_xor_sync(0xffffffffu, s, o);
    if (lane == 0) {
        if (rowId < HH) g_rsWr[h] = s;
        else            g_rsW[h]  = s;
    }
}

// ---------------- gate MLP: tf32 mma.sync + fused z-build + tanh + z2 dot -----
// grid (S/128, 512/128, B), 256 threads = 8 warps (4 s x 2 j).
__global__ void __launch_bounds__(256, 2) gate_kernel(
    const float* __restrict__ facts, const float* __restrict__ q,
    const float* __restrict__ m, const float* __restrict__ z1w,
    const float* __restrict__ z1b, const float* __restrict__ z2w)
{
    extern __shared__ __align__(16) float gsm[];
    float* As   = gsm;                   // [4][16][132] tf32 z-variants (k-major)
    float* Bs   = As + 4 * 16 * 132;     // [4][16][132] tf32 z1w tile (k-major)
    float* qs   = Bs + 4 * 16 * 132;     // [512]
    float* ms   = qs + HH;               // [512]
    float* z1bs = ms + HH;               // [128]
    float* z2ws = z1bs + 128;            // [128]
    float* ps   = z2ws + 128;            // [8][32] per-warp s-partials

    int tid = threadIdx.x;
    int b  = blockIdx.z;
    int s0 = blockIdx.x * 128;
    int j0 = blockIdx.y * 128;
    int wid = tid >> 5, lane = tid & 31;
    int ws = wid >> 1, wj = wid & 1;      // warp grid 4(s) x 2(j)
    int gp = lane >> 2, tg = lane & 3;    // mma group / thread-in-group

    for (int i = tid; i < HH; i += 256) {
        qs[i] = q[b * HH + i];
        ms[i] = m[b * HH + i];
    }
    if (tid < 128) {
        z1bs[tid] = z1b[j0 + tid];
        z2ws[tid] = z2w[j0 + tid];
    }

    const float* fb = facts + ((size_t)b * SS + s0) * HH;

    float acc[2][8][4];                   // [s-subtile][j-subtile][frag]
#pragma unroll
    for (int i = 0; i < 2; i++)
#pragma unroll
        for (int j = 0; j < 8; j++)
#pragma unroll
            for (int k = 0; k < 4; k++) acc[i][j][k] = 0.f;

    for (int c = 0; c < 32; c++) {        // 32 chunks of 16 facts-k
        int k0 = c * 16;
        __syncthreads();                  // prev compute done (covers qs/ms @c=0)

        // build As: 4 tf32 z-variants of the facts k-chunk
#pragma unroll
        for (int r = 0; r < 8; r++) {
            int idx = tid + r * 256;
            int ss = idx >> 4, kk = idx & 15;
            float fv = fb[(size_t)ss * HH + k0 + kk];
            float qv = qs[k0 + kk], mv = ms[k0 + kk];
            As[(0 * 16 + kk) * 132 + ss] = to_tf32(fv * qv);
            As[(1 * 16 + kk) * 132 + ss] = to_tf32(fv * mv);
            As[(2 * 16 + kk) * 132 + ss] = to_tf32(fabsf(fv - qv));
            As[(3 * 16 + kk) * 132 + ss] = to_tf32(fabsf(fv - mv));
        }
        // stage Bs: z1w rows {v*512 + k0 + kk}, cols j0..j0+127, as tf32
#pragma unroll
        for (int r = 0; r < 8; r++) {
            int idx = tid + r * 256;        // float4 index 0..2047
            int row = idx >> 5;             // 0..63: v = row>>4, kk = row&15
            int c4 = idx & 31;
            float4 v4 = *reinterpret_cast<const float4*>(
                &z1w[(size_t)((row >> 4) * HH + k0 + (row & 15)) * HH + j0 + c4 * 4]);
            float* dst = &Bs[row * 132 + c4 * 4];
            dst[0] = to_tf32(v4.x); dst[1] = to_tf32(v4.y);
            dst[2] = to_tf32(v4.z); dst[3] = to_tf32(v4.w);
        }
        __syncthreads();                  // As/Bs ready

        // compute: 4 variants x 2 k8-substeps
#pragma unroll
        for (int sub = 0; sub < 8; sub++) {
            int v = sub >> 1, k8 = (sub & 1) * 8;
            const float* Av = &As[v * 16 * 132];
            const float* Bv = &Bs[v * 16 * 132];
            unsigned a[2][4];
#pragma unroll
            for (int st = 0; st < 2; st++) {
                int row0 = ws * 32 + st * 16 + gp;
                a[st][0] = __float_as_uint(Av[(k8 + tg) * 132 + row0]);
                a[st][1] = __float_as_uint(Av[(k8 + tg) * 132 + row0 + 8]);
                a[st][2] = __float_as_uint(Av[(k8 + tg + 4) * 132 + row0]);
                a[st][3] = __float_as_uint(Av[(k8 + tg + 4) * 132 + row0 + 8]);
            }
#pragma unroll
            for (int jt = 0; jt < 8; jt++) {
                int n0 = wj * 64 + jt * 8 + gp;
                unsigned b0 = __float_as_uint(Bv[(k8 + tg) * 132 + n0]);
                unsigned b1 = __float_as_uint(Bv[(k8 + tg + 4) * 132 + n0]);
                mma_tf32(acc[0][jt], a[0], b0, b1);
                mma_tf32(acc[1][jt], a[1], b0, b1);
            }
        }
    }

    // epilogue: tanh(acc + z1b) . z2w, reduce over this block's 128 j
#pragma unroll
    for (int st = 0; st < 2; st++) {
        float s_r0 = 0.f, s_r1 = 0.f;
#pragma unroll
        for (int jt = 0; jt < 8; jt++) {
#pragma unroll
            for (int ci = 0; ci < 2; ci++) {
                int col = wj * 64 + jt * 8 + tg * 2 + ci;
                float zb = z1bs[col], zw = z2ws[col];
                s_r0 = fmaf(tanh_approx(acc[st][jt][ci] + zb), zw, s_r0);
                s_r1 = fmaf(tanh_approx(acc[st][jt][2 + ci] + zb), zw, s_r1);
            }
        }
#pragma unroll
        for (int o = 1; o <= 2; o <<= 1) {
            s_r0 += __shfl_xor_sync(0xffffffffu, s_r0, o);
            s_r1 += __shfl_xor_sync(0xffffffffu, s_r1, o);
        }
        if (tg == 0) {
            ps[wid * 32 + st * 16 + gp]     = s_r0;
            ps[wid * 32 + st * 16 + 8 + gp] = s_r1;
        }
    }
    __syncthreads();
    if (tid < 128) {
        int wsx = tid >> 5, wi = tid & 31;
        float v = ps[(wsx * 2 + 0) * 32 + wi] + ps[(wsx * 2 + 1) * 32 + wi];
        g_part[blockIdx.y][b * SS + s0 + tid] = v;
    }
}

// ---------------- softmax over S per batch (also zeroes scan flags) -----------
__global__ void softmax_kernel()
{
    int b = blockIdx.x, s = threadIdx.x;   // 256 threads
    if (b == 0) g_flags[s >> 5][s & 31] = 0u;  // zero all padded flag words
    float l = 0.f;
#pragma unroll
    for (int jb = 0; jb < 4; jb++) l += g_part[jb][b * SS + s];
    __shared__ float sm[256];
    sm[s] = l;
    __syncthreads();
#pragma unroll
    for (int o = 128; o > 0; o >>= 1) {
        if (s < o) sm[s] = fmaxf(sm[s], sm[s + o]);
        __syncthreads();
    }
    float mx = sm[0];
    __syncthreads();
    float e = expf(l - mx);
    sm[s] = e;
    __syncthreads();
#pragma unroll
    for (int o = 128; o > 0; o >>= 1) {
        if (s < o) sm[s] += sm[s + o];
        __syncthreads();
    }
    g_Gt[s * BB + b] = e / sm[0];
}

// ---------------- persistent scan: 256 blocks = 32 hg x 8 bg, 2 blocks/SM -----
// Block owns 16 h x 16 b, 256 threads. Weights (64KB) persist in smem; two
// co-resident blocks per SM hide each other's poll/reduce/barrier stalls.
// Thread (compute): ks(8) x [hq(8) x bq(4)]; tile 2h x 4b x {R,U}.
__global__ void __launch_bounds__(256, 2) scan_persist(
    const float* __restrict__ facts,
    const float* __restrict__ Ur, const float* __restrict__ U,
    const float* __restrict__ br, const float* __restrict__ bur,
    const float* __restrict__ bw, const float* __restrict__ bu)
{
    extern __shared__ __align__(16) char dsm[];
    u64* wpk = reinterpret_cast<u64*>(dsm);           // [512][16]: pk2(Ur, U)
    u64* red = reinterpret_cast<u64*>(dsm + 65536);   // [8][8][33] padded

    __shared__ float hcs[5][16];

    int tid = threadIdx.x;
    int hg = blockIdx.x >> 3;      // 0..31
    int bg = blockIdx.x & 7;       // 0..7
    int h0 = hg * 16;
    int b0 = bg * 16;

    // one-time: pack (R,U) weight pairs for this 16-h slice
    for (int idx = tid; idx < 512 * 16; idx += 256) {
        int k = idx >> 4, h = idx & 15;
        wpk[idx] = pk2(Ur[(size_t)k * HH + h0 + h], U[(size_t)k * HH + h0 + h]);
    }
    if (tid < 16) {
        int h = h0 + tid;
        hcs[0][tid] = g_rsWr[h];
        hcs[1][tid] = br[h] + bur[h];
        hcs[2][tid] = g_rsW[h];
        hcs[3][tid] = bw[h];
        hcs[4][tid] = bu[h];
    }
    __syncthreads();

    // compute mapping: ks(8) x lane(32) = hq(8, 2h each) x bq(4, 4b each)
    int ks = tid >> 5;
    int lane = tid & 31;
    int hq = lane >> 2, bq = lane & 3;

    // reduce/epilogue mapping: one (h,b) per thread
    int ep_pos = tid >> 3, ep_i = tid & 7;          // i = bb*2 + hh
    int e_hq = ep_pos >> 2, e_bq = ep_pos & 3;
    int e_hh = ep_i & 1,   e_bb = ep_i >> 1;        // hh fastest -> facts pairs
    int ehl = e_hq * 2 + e_hh;                      // local h 0..15
    int eh  = h0 + ehl;
    int eb  = b0 + e_bq * 4 + e_bb;
    float cur_c = 0.f;

    for (int s = 0; s < SS; s++) {
        u64 aRU = 0ull;

        if (s > 0) {
            // lane0-acquire poll: all 32 producers of this bg finished step s-1
            unsigned target = 32u * (unsigned)s;
            if (lane == 0) {
                while (ld_acq(&g_flags[bg][0]) < target) {}
            }
            __syncwarp();   // extend lane0's acquire to the whole warp

            const float* __restrict__ Cin = g_C[s & 1];
            u64 acc[2][4];
#pragma unroll
            for (int i = 0; i < 2; i++)
#pragma unroll
                for (int j = 0; j < 4; j++) acc[i][j] = 0ull;

            const float4* cp = reinterpret_cast<const float4*>(
                Cin + (size_t)(ks * 64) * BB + b0 + bq * 4);
#pragma unroll 4
            for (int kk = 0; kk < 64; kk++) {
                float4 cv = __ldcg(cp + (size_t)kk * (BB / 4));
                u64 cd[4] = {pk2(cv.x, cv.x), pk2(cv.y, cv.y),
                             pk2(cv.z, cv.z), pk2(cv.w, cv.w)};
                ulonglong2 w01 = *reinterpret_cast<const ulonglong2*>(
                    &wpk[(ks * 64 + kk) * 16 + hq * 2]);
#pragma unroll
                for (int bb = 0; bb < 4; bb++) {
                    acc[0][bb] = fma2_(cd[bb], w01.x, acc[0][bb]);
                    acc[1][bb] = fma2_(cd[bb], w01.y, acc[1][bb]);
                }
            }

            // write k-split partials: i = bb*2 + hh
#pragma unroll
            for (int hh = 0; hh < 2; hh++)
#pragma unroll
                for (int bb = 0; bb < 4; bb++)
                    red[(size_t)(ks * 8 + bb * 2 + hh) * 33 + lane] = acc[hh][bb];
            __syncthreads();

            // each thread sums its 8 k-split partials for its own (h,b)
            u64 v = red[(size_t)ep_i * 33 + ep_pos];
#pragma unroll
            for (int t = 1; t < 8; t++)
                v = add2_(v, red[(size_t)(t * 8 + ep_i) * 33 + ep_pos]);
            aRU = v;
        }

        // fused epilogue: nonlinearity + blend; C kept in a register
        {
            float aR, aU;
            upk2(aRU, aR, aU);
            float* __restrict__ Cout = g_C[(s + 1) & 1];
            float fv = __ldg(facts + ((size_t)eb * SS + s) * HH + eh);
            float g = g_Gt[s * BB + eb];
            float rr = 1.f / (1.f + expf(-(fmaf(fv, hcs[0][ehl], hcs[1][ehl]) + aR)));
            float ht = tanhf(fmaf(rr, aU + hcs[4][ehl],
                                  fmaf(fv, hcs[2][ehl], hcs[3][ehl])));
            cur_c = fmaf(g, ht - cur_c, cur_c);
            __stcg(&Cout[(size_t)eh * BB + eb], cur_c);
        }
        __syncthreads();       // all C stores in this block issued (program order)
        if (tid == 0) red_add_rel(&g_flags[bg][0], 1u);
    }
}

// ---------------- final: relu(concat @ nm_w + nm_b) ---------------------------
__global__ void __launch_bounds__(512) final_kernel(
    const float* __restrict__ prevM, const float* __restrict__ q,
    const float* __restrict__ nm_w, const float* __restrict__ nm_b,
    float* __restrict__ out)
{
    __shared__ float cs[3 * HH];
    int b = blockIdx.x, tid = threadIdx.x;    // 512 threads
    cs[tid]          = prevM[b * HH + tid];
    cs[HH + tid]     = g_C[0][(size_t)tid * BB + b];   // final C lives in buffer 0
    cs[2 * HH + tid] = q[b * HH + tid];
    __syncthreads();
    float acc = nm_b[tid];
#pragma unroll 8
    for (int k = 0; k < 3 * HH; k++)
        acc = fmaf(cs[k], nm_w[(size_t)k * HH + tid], acc);
    out[b * HH + tid] = fmaxf(acc, 0.f);
}

// ---------------- launch -------------------------------------------------------
extern "C" void kernel_launch(void* const* d_in, const int* in_sizes, int n_in,
                              void* d_out, int out_size)
{
    const float* facts     = (const float*)d_in[0];
    const float* questions = (const float*)d_in[1];
    const float* prevM     = (const float*)d_in[2];
    const float* z1_w      = (const float*)d_in[3];
    const float* z1_b      = (const float*)d_in[4];
    const float* z2_w      = (const float*)d_in[5];
    // d_in[6] z2_b: constant shift, softmax-invariant — unused
    const float* Wr        = (const float*)d_in[7];
    const float* br        = (const float*)d_in[8];
    const float* Ur        = (const float*)d_in[9];
    const float* bur       = (const float*)d_in[10];
    const float* W         = (const float*)d_in[11];
    const float* bw        = (const float*)d_in[12];
    const float* U         = (const float*)d_in[13];
    const float* bu        = (const float*)d_in[14];
    const float* nm_w      = (const float*)d_in[15];
    const float* nm_b      = (const float*)d_in[16];
    float* out = (float*)d_out;

    const int scan_smem = 65536 + 8 * 8 * 33 * 8;      // wpk + red = 82432
    cudaFuncSetAttribute(scan_persist,
                         cudaFuncAttributeMaxDynamicSharedMemorySize, scan_smem);
    const int gate_smem = (2 * 4 * 16 * 132 + 2 * HH + 2 * 128 + 256) * 4; // 73728
    cudaFuncSetAttribute(gate_kernel,
                         cudaFuncAttributeMaxDynamicSharedMemorySize, gate_smem);

    prep_kernel<<<128, 256>>>(Wr, W);
    gate_kernel<<<dim3(2, 4, BB), 256, gate_smem>>>(facts, questions, prevM,
                                                    z1_w, z1_b, z2_w);
    softmax_kernel<<<BB, 256>>>();
    scan_persist<<<256, 256, scan_smem>>>(facts, Ur, U, br, bur, bw, bu);
    final_kernel<<<BB, 512>>>(prevM, questions, nm_w, nm_b, out);
}

// round 13
// speedup vs baseline: 1.1928x; 1.1928x over previous
#include <cuda_runtime.h>
#include <math.h>

#define BB 128
#define SS 256
#define HH 512

typedef unsigned long long u64;

// ---------------- device scratch (no allocations allowed) -------------------
__device__ float g_rsWr[HH];            // rowsum(Wr)
__device__ float g_rsW[HH];             // rowsum(W)
__device__ float g_part[4][BB * SS];    // per-jblock logit partials
__device__ float g_Gt[SS * BB];         // softmax gates, (s, b)
__device__ float g_C[2][HH * BB];       // recurrent state, transposed (h, b)
__device__ unsigned g_flags[8][32];     // per-bg step counters, 128B padded

// ---------------- f32x2 / misc helpers ----------------------------------------
__device__ __forceinline__ u64 pk2(float x, float y) {
    u64 r;
    asm("mov.b64 %0, {%1,%2};" : "=l"(r) : "f"(x), "f"(y));
    return r;
}
__device__ __forceinline__ void upk2(u64 v, float& x, float& y) {
    asm("mov.b64 {%0,%1}, %2;" : "=f"(x), "=f"(y) : "l"(v));
}
__device__ __forceinline__ u64 fma2_(u64 a, u64 b, u64 c) {
    u64 d;
    asm("fma.rn.f32x2 %0, %1, %2, %3;" : "=l"(d) : "l"(a), "l"(b), "l"(c));
    return d;
}
__device__ __forceinline__ u64 add2_(u64 a, u64 b) {
    u64 d;
    asm("add.rn.f32x2 %0, %1, %2;" : "=l"(d) : "l"(a), "l"(b));
    return d;
}
__device__ __forceinline__ float tanh_approx(float x) {
    float y;
    asm("tanh.approx.f32 %0, %1;" : "=f"(y) : "f"(x));
    return y;
}
__device__ __forceinline__ float to_tf32(float x) {
    float y;
    asm("cvt.rna.tf32.f32 %0, %1;" : "=f"(y) : "f"(x));
    return y;
}
__device__ __forceinline__ unsigned ld_acq(const unsigned* p) {
    unsigned v;
    asm volatile("ld.acquire.gpu.global.u32 %0, [%1];" : "=r"(v) : "l"(p));
    return v;
}
__device__ __forceinline__ void red_add_rel(unsigned* p, unsigned v) {
    asm volatile("red.add.release.gpu.global.u32 [%0], %1;" :: "l"(p), "r"(v) : "memory");
}
__device__ __forceinline__ void mma_tf32(float* d, const unsigned* a,
                                         unsigned b0, unsigned b1) {
    asm volatile(
        "mma.sync.aligned.m16n8k8.row.col.f32.tf32.tf32.f32 "
        "{%0,%1,%2,%3}, {%4,%5,%6,%7}, {%8,%9}, {%0,%1,%2,%3};"
        : "+f"(d[0]), "+f"(d[1]), "+f"(d[2]), "+f"(d[3])
        : "r"(a[0]), "r"(a[1]), "r"(a[2]), "r"(a[3]), "r"(b0), "r"(b1));
}

// ---------------- prep: rowsums of Wr and W ----------------------------------
__global__ void prep_kernel(const float* __restrict__ Wr, const float* __restrict__ W)
{
    int warp = threadIdx.x >> 5, lane = threadIdx.x & 31;
    int rowId = blockIdx.x * 8 + warp;               // 0..1023
    const float* src = (rowId < HH) ? Wr : W;
    int h = rowId & (HH - 1);
    const float4* s4 = reinterpret_cast<const float4*>(src + (size_t)h * HH);
    float s = 0.f;
    for (int i = lane; i < HH / 4; i += 32) {
        float4 v = s4[i];
        s += (v.x + v.y) + (v.z + v.w);
    }
#pragma unroll
    for (int o = 16; o > 0; o >>= 1) s += __shfl_xor_sync(0xffffffffu, s, o);
    if (lane == 0) {
        if (rowId < HH) g_rsWr[h] = s;
        else            g_rsW[h]  = s;
    }
}

// ---------------- gate MLP: tf32 mma.sync + fused z-build + tanh + z2 dot -----
// grid (S/128, 512/128, B), 256 threads = 8 warps (4 s x 2 j).
// facts + half the z1w tile register-prefetched one chunk ahead.
__global__ void __launch_bounds__(256, 2) gate_kernel(
    const float* __restrict__ facts, const float* __restrict__ q,
    const float* __restrict__ m, const float* __restrict__ z1w,
    const float* __restrict__ z1b, const float* __restrict__ z2w)
{
    extern __shared__ __align__(16) float gsm[];
    float* As   = gsm;                   // [4][16][132] tf32 z-variants (k-major)
    float* Bs   = As + 4 * 16 * 132;     // [4][16][132] tf32 z1w tile (k-major)
    float* qs   = Bs + 4 * 16 * 132;     // [512]
    float* ms   = qs + HH;               // [512]
    float* z1bs = ms + HH;               // [128]
    float* z2ws = z1bs + 128;            // [128]
    float* ps   = z2ws + 128;            // [8][32] per-warp s-partials

    int tid = threadIdx.x;
    int b  = blockIdx.z;
    int s0 = blockIdx.x * 128;
    int j0 = blockIdx.y * 128;
    int wid = tid >> 5, lane = tid & 31;
    int ws = wid >> 1, wj = wid & 1;      // warp grid 4(s) x 2(j)
    int gp = lane >> 2, tg = lane & 3;    // mma group / thread-in-group

    for (int i = tid; i < HH; i += 256) {
        qs[i] = q[b * HH + i];
        ms[i] = m[b * HH + i];
    }
    if (tid < 128) {
        z1bs[tid] = z1b[j0 + tid];
        z2ws[tid] = z2w[j0 + tid];
    }

    const float* fb = facts + ((size_t)b * SS + s0) * HH;

    // fixed sub-indices
    int a_ss[8], a_kk[8];
#pragma unroll
    for (int r = 0; r < 8; r++) { int i = tid + r * 256; a_ss[r] = i >> 4; a_kk[r] = i & 15; }
    int b_row[8], b_c4[8];
#pragma unroll
    for (int r = 0; r < 8; r++) { int i = tid + r * 256; b_row[r] = i >> 5; b_c4[r] = i & 31; }

    // prefetch chunk 0: facts (all) + z1w rows 0..31 (variants 0,1)
    float freg[8];
#pragma unroll
    for (int r = 0; r < 8; r++) freg[r] = fb[(size_t)a_ss[r] * HH + a_kk[r]];
    float4 breg[4];
#pragma unroll
    for (int r = 0; r < 4; r++)
        breg[r] = *reinterpret_cast<const float4*>(
            &z1w[(size_t)((b_row[r] >> 4) * HH + (b_row[r] & 15)) * HH + j0 + b_c4[r] * 4]);

    float acc[2][8][4];                   // [s-subtile][j-subtile][frag]
#pragma unroll
    for (int i = 0; i < 2; i++)
#pragma unroll
        for (int j = 0; j < 8; j++)
#pragma unroll
            for (int k = 0; k < 4; k++) acc[i][j][k] = 0.f;

    for (int c = 0; c < 32; c++) {        // 32 chunks of 16 facts-k
        int k0 = c * 16;
        __syncthreads();                  // compute c-1 done (covers qs/ms @c=0)

        // build As from prefetched facts
#pragma unroll
        for (int r = 0; r < 8; r++) {
            float fv = freg[r];
            int kk = k0 + a_kk[r];
            float qv = qs[kk], mv = ms[kk];
            As[(0 * 16 + a_kk[r]) * 132 + a_ss[r]] = to_tf32(fv * qv);
            As[(1 * 16 + a_kk[r]) * 132 + a_ss[r]] = to_tf32(fv * mv);
            As[(2 * 16 + a_kk[r]) * 132 + a_ss[r]] = to_tf32(fabsf(fv - qv));
            As[(3 * 16 + a_kk[r]) * 132 + a_ss[r]] = to_tf32(fabsf(fv - mv));
        }
        // Bs rows 0..31 from prefetched regs
#pragma unroll
        for (int r = 0; r < 4; r++) {
            float* dst = &Bs[b_row[r] * 132 + b_c4[r] * 4];
            dst[0] = to_tf32(breg[r].x); dst[1] = to_tf32(breg[r].y);
            dst[2] = to_tf32(breg[r].z); dst[3] = to_tf32(breg[r].w);
        }
        // Bs rows 32..63 (variants 2,3) loaded directly
#pragma unroll
        for (int r = 4; r < 8; r++) {
            float4 v4 = *reinterpret_cast<const float4*>(
                &z1w[(size_t)((b_row[r] >> 4) * HH + k0 + (b_row[r] & 15)) * HH + j0 + b_c4[r] * 4]);
            float* dst = &Bs[b_row[r] * 132 + b_c4[r] * 4];
            dst[0] = to_tf32(v4.x); dst[1] = to_tf32(v4.y);
            dst[2] = to_tf32(v4.z); dst[3] = to_tf32(v4.w);
        }
        // prefetch chunk c+1 (flies during sync + compute)
        if (c < 31) {
            int k0n = k0 + 16;
#pragma unroll
            for (int r = 0; r < 8; r++)
                freg[r] = fb[(size_t)a_ss[r] * HH + k0n + a_kk[r]];
#pragma unroll
            for (int r = 0; r < 4; r++)
                breg[r] = *reinterpret_cast<const float4*>(
                    &z1w[(size_t)((b_row[r] >> 4) * HH + k0n + (b_row[r] & 15)) * HH + j0 + b_c4[r] * 4]);
        }
        __syncthreads();                  // As/Bs ready

        // compute: 4 variants x 2 k8-substeps
#pragma unroll
        for (int sub = 0; sub < 8; sub++) {
            int v = sub >> 1, k8 = (sub & 1) * 8;
            const float* Av = &As[v * 16 * 132];
            const float* Bv = &Bs[v * 16 * 132];
            unsigned a[2][4];
#pragma unroll
            for (int st = 0; st < 2; st++) {
                int row0 = ws * 32 + st * 16 + gp;
                a[st][0] = __float_as_uint(Av[(k8 + tg) * 132 + row0]);
                a[st][1] = __float_as_uint(Av[(k8 + tg) * 132 + row0 + 8]);
                a[st][2] = __float_as_uint(Av[(k8 + tg + 4) * 132 + row0]);
                a[st][3] = __float_as_uint(Av[(k8 + tg + 4) * 132 + row0 + 8]);
            }
#pragma unroll
            for (int jt = 0; jt < 8; jt++) {
                int n0 = wj * 64 + jt * 8 + gp;
                unsigned b0 = __float_as_uint(Bv[(k8 + tg) * 132 + n0]);
                unsigned b1 = __float_as_uint(Bv[(k8 + tg + 4) * 132 + n0]);
                mma_tf32(acc[0][jt], a[0], b0, b1);
                mma_tf32(acc[1][jt], a[1], b0, b1);
            }
        }
    }

    // epilogue: tanh(acc + z1b) . z2w, reduce over this block's 128 j
#pragma unroll
    for (int st = 0; st < 2; st++) {
        float s_r0 = 0.f, s_r1 = 0.f;
#pragma unroll
        for (int jt = 0; jt < 8; jt++) {
#pragma unroll
            for (int ci = 0; ci < 2; ci++) {
                int col = wj * 64 + jt * 8 + tg * 2 + ci;
                float zb = z1bs[col], zw = z2ws[col];
                s_r0 = fmaf(tanh_approx(acc[st][jt][ci] + zb), zw, s_r0);
                s_r1 = fmaf(tanh_approx(acc[st][jt][2 + ci] + zb), zw, s_r1);
            }
        }
#pragma unroll
        for (int o = 1; o <= 2; o <<= 1) {
            s_r0 += __shfl_xor_sync(0xffffffffu, s_r0, o);
            s_r1 += __shfl_xor_sync(0xffffffffu, s_r1, o);
        }
        if (tg == 0) {
            ps[wid * 32 + st * 16 + gp]     = s_r0;
            ps[wid * 32 + st * 16 + 8 + gp] = s_r1;
        }
    }
    __syncthreads();
    if (tid < 128) {
        int wsx = tid >> 5, wi = tid & 31;
        float v = ps[(wsx * 2 + 0) * 32 + wi] + ps[(wsx * 2 + 1) * 32 + wi];
        g_part[blockIdx.y][b * SS + s0 + tid] = v;
    }
}

// ---------------- softmax over S per batch (also zeroes scan flags) -----------
__global__ void softmax_kernel()
{
    int b = blockIdx.x, s = threadIdx.x;   // 256 threads
    if (b == 0) g_flags[s >> 5][s & 31] = 0u;  // zero all padded flag words
    float l = 0.f;
#pragma unroll
    for (int jb = 0; jb < 4; jb++) l += g_part[jb][b * SS + s];
    __shared__ float sm[256];
    sm[s] = l;
    __syncthreads();
#pragma unroll
    for (int o = 128; o > 0; o >>= 1) {
        if (s < o) sm[s] = fmaxf(sm[s], sm[s + o]);
        __syncthreads();
    }
    float mx = sm[0];
    __syncthreads();
    float e = expf(l - mx);
    sm[s] = e;
    __syncthreads();
#pragma unroll
    for (int o = 128; o > 0; o >>= 1) {
        if (s < o) sm[s] += sm[s + o];
        __syncthreads();
    }
    g_Gt[s * BB + b] = e / sm[0];
}

// ---------------- persistent scan: 128 blocks = 16 hg x 8 bg (R10 verbatim) ---
__global__ void __launch_bounds__(512, 1) scan_persist(
    const float* __restrict__ facts,
    const float* __restrict__ Ur, const float* __restrict__ U,
    const float* __restrict__ br, const float* __restrict__ bur,
    const float* __restrict__ bw, const float* __restrict__ bu)
{
    extern __shared__ __align__(16) char dsm[];
    u64* wpk = reinterpret_cast<u64*>(dsm);            // [512][32]: pk2(Ur, U)
    u64* red = reinterpret_cast<u64*>(dsm + 131072);   // [16][16][33] padded

    __shared__ float hcs[5][32];

    int tid = threadIdx.x;
    int hg = blockIdx.x >> 3;      // 0..15
    int bg = blockIdx.x & 7;       // 0..7
    int h0 = hg * 32;
    int b0 = bg * 16;

    // one-time: pack (R,U) weight pairs for this h-slice
    for (int idx = tid; idx < 512 * 32; idx += 512) {
        int k = idx >> 5, h = idx & 31;
        wpk[idx] = pk2(Ur[(size_t)k * HH + h0 + h], U[(size_t)k * HH + h0 + h]);
    }
    if (tid < 32) {
        int h = h0 + tid;
        hcs[0][tid] = g_rsWr[h];
        hcs[1][tid] = br[h] + bur[h];
        hcs[2][tid] = g_rsW[h];
        hcs[3][tid] = bw[h];
        hcs[4][tid] = bu[h];
    }
    __syncthreads();

    // compute mapping
    int ks = tid >> 5;
    int lane = tid & 31;
    int hq = lane >> 2, bq = lane & 3;

    // reduce/epilogue mapping: one (h,b) per thread, fixed across steps
    int ep_pos = tid >> 4, ep_i = tid & 15;
    int e_hq = ep_pos >> 2, e_bq = ep_pos & 3;
    int e_hh = ep_i & 3,   e_bb = ep_i >> 2;        // hh fastest -> coalesced facts
    int ehl = e_hq * 4 + e_hh;                      // local h
    int eh  = h0 + ehl;
    int eb  = b0 + e_bq * 4 + e_bb;
    float cur_c = 0.f;

    for (int s = 0; s < SS; s++) {
        u64 aRU = 0ull;

        if (s > 0) {
            // lane0-acquire poll: all 16 producers of this bg finished step s-1
            unsigned target = 16u * (unsigned)s;
            if (lane == 0) {
                while (ld_acq(&g_flags[bg][0]) < target) {}
            }
            __syncwarp();   // extend lane0's acquire to the whole warp

            const float* __restrict__ Cin = g_C[s & 1];
            u64 acc[4][4];
#pragma unroll
            for (int i = 0; i < 4; i++)
#pragma unroll
                for (int j = 0; j < 4; j++) acc[i][j] = 0ull;

            const float4* cp = reinterpret_cast<const float4*>(
                Cin + (size_t)(ks * 32) * BB + b0 + bq * 4);
#pragma unroll 4
            for (int kk = 0; kk < 32; kk++) {
                float4 cv = __ldcg(cp + (size_t)kk * (BB / 4));
                u64 cd[4] = {pk2(cv.x, cv.x), pk2(cv.y, cv.y),
                             pk2(cv.z, cv.z), pk2(cv.w, cv.w)};
                const u64* wr = &wpk[(ks * 32 + kk) * 32 + hq * 4];
                ulonglong2 w01 = *reinterpret_cast<const ulonglong2*>(wr);
                ulonglong2 w23 = *reinterpret_cast<const ulonglong2*>(wr + 2);
                u64 w[4] = {w01.x, w01.y, w23.x, w23.y};
#pragma unroll
                for (int hh = 0; hh < 4; hh++)
#pragma unroll
                    for (int bb = 0; bb < 4; bb++)
                        acc[hh][bb] = fma2_(cd[bb], w[hh], acc[hh][bb]);
            }

            // write k-split partials (prev step's red reads sealed by last sync)
#pragma unroll
            for (int hh = 0; hh < 4; hh++)
#pragma unroll
                for (int bb = 0; bb < 4; bb++) {
                    int i = bb * 4 + hh;
                    red[(size_t)(ks * 16 + i) * 33 + lane] = acc[hh][bb];
                }
            __syncthreads();

            // each thread sums its 16 k-split partials for its own (h,b)
            u64 v = red[(size_t)ep_i * 33 + ep_pos];
#pragma unroll
            for (int t = 1; t < 16; t++)
                v = add2_(v, red[(size_t)(t * 16 + ep_i) * 33 + ep_pos]);
            aRU = v;
        }

        // fused epilogue: nonlinearity + blend; C kept in a register
        {
            float aR, aU;
            upk2(aRU, aR, aU);
            float* __restrict__ Cout = g_C[(s + 1) & 1];
            float fv = __ldg(facts + ((size_t)eb * SS + s) * HH + eh);
            float g = g_Gt[s * BB + eb];
            float rr = 1.f / (1.f + expf(-(fmaf(fv, hcs[0][ehl], hcs[1][ehl]) + aR)));
            float ht = tanhf(fmaf(rr, aU + hcs[4][ehl],
                                  fmaf(fv, hcs[2][ehl], hcs[3][ehl])));
            cur_c = fmaf(g, ht - cur_c, cur_c);
            __stcg(&Cout[(size_t)eh * BB + eb], cur_c);
        }
        __syncthreads();       // all C stores in this block issued (program order)
        if (tid == 0) red_add_rel(&g_flags[bg][0], 1u);
    }
}

// ---------------- final: relu(concat @ nm_w + nm_b) ---------------------------
__global__ void __launch_bounds__(512) final_kernel(
    const float* __restrict__ prevM, const float* __restrict__ q,
    const float* __restrict__ nm_w, const float* __restrict__ nm_b,
    float* __restrict__ out)
{
    __shared__ float cs[3 * HH];
    int b = blockIdx.x, tid = threadIdx.x;    // 512 threads
    cs[tid]          = prevM[b * HH + tid];
    cs[HH + tid]     = g_C[0][(size_t)tid * BB + b];   // final C lives in buffer 0
    cs[2 * HH + tid] = q[b * HH + tid];
    __syncthreads();
    float acc = nm_b[tid];
#pragma unroll 8
    for (int k = 0; k < 3 * HH; k++)
        acc = fmaf(cs[k], nm_w[(size_t)k * HH + tid], acc);
    out[b * HH + tid] = fmaxf(acc, 0.f);
}

// ---------------- launch -------------------------------------------------------
extern "C" void kernel_launch(void* const* d_in, const int* in_sizes, int n_in,
                              void* d_out, int out_size)
{
    const float* facts     = (const float*)d_in[0];
    const float* questions = (const float*)d_in[1];
    const float* prevM     = (const float*)d_in[2];
    const float* z1_w      = (const float*)d_in[3];
    const float* z1_b      = (const float*)d_in[4];
    const float* z2_w      = (const float*)d_in[5];
    // d_in[6] z2_b: constant shift, softmax-invariant — unused
    const float* Wr        = (const float*)d_in[7];
    const float* br        = (const float*)d_in[8];
    const float* Ur        = (const float*)d_in[9];
    const float* bur       = (const float*)d_in[10];
    const float* W         = (const float*)d_in[11];
    const float* bw        = (const float*)d_in[12];
    const float* U         = (const float*)d_in[13];
    const float* bu        = (const float*)d_in[14];
    const float* nm_w      = (const float*)d_in[15];
    const float* nm_b      = (const float*)d_in[16];
    float* out = (float*)d_out;

    const int scan_smem = 131072 + 16 * 16 * 33 * 8;   // wpk + red = 198656
    cudaFuncSetAttribute(scan_persist,
                         cudaFuncAttributeMaxDynamicSharedMemorySize, scan_smem);
    const int gate_smem = (2 * 4 * 16 * 132 + 2 * HH + 2 * 128 + 256) * 4; // 73728
    cudaFuncSetAttribute(gate_kernel,
                         cudaFuncAttributeMaxDynamicSharedMemorySize, gate_smem);

    prep_kernel<<<128, 256>>>(Wr, W);
    gate_kernel<<<dim3(2, 4, BB), 256, gate_smem>>>(facts, questions, prevM,
                                                    z1_w, z1_b, z2_w);
    softmax_kernel<<<BB, 256>>>();
    scan_persist<<<128, 512, scan_smem>>>(facts, Ur, U, br, bur, bw, bu);
    final_kernel<<<BB, 512>>>(prevM, questions, nm_w, nm_b, out);
}

// round 14
// speedup vs baseline: 1.2424x; 1.0416x over previous
#include <cuda_runtime.h>
#include <math.h>

#define BB 128
#define SS 256
#define HH 512

typedef unsigned long long u64;

// ---------------- device scratch (no allocations allowed) -------------------
__device__ float g_rsWr[HH];            // rowsum(Wr)
__device__ float g_rsW[HH];             // rowsum(W)
__device__ float g_part[4][BB * SS];    // per-jblock logit partials
__device__ float g_Gt[SS * BB];         // softmax gates, (s, b)
__device__ float g_C[2][HH * BB];       // recurrent state, transposed (h, b)
__device__ unsigned g_flagp[8][16][32]; // per-(bg,hg) step flag, 128B padded

// ---------------- f32x2 / misc helpers ----------------------------------------
__device__ __forceinline__ u64 pk2(float x, float y) {
    u64 r;
    asm("mov.b64 %0, {%1,%2};" : "=l"(r) : "f"(x), "f"(y));
    return r;
}
__device__ __forceinline__ void upk2(u64 v, float& x, float& y) {
    asm("mov.b64 {%0,%1}, %2;" : "=f"(x), "=f"(y) : "l"(v));
}
__device__ __forceinline__ u64 fma2_(u64 a, u64 b, u64 c) {
    u64 d;
    asm("fma.rn.f32x2 %0, %1, %2, %3;" : "=l"(d) : "l"(a), "l"(b), "l"(c));
    return d;
}
__device__ __forceinline__ u64 add2_(u64 a, u64 b) {
    u64 d;
    asm("add.rn.f32x2 %0, %1, %2;" : "=l"(d) : "l"(a), "l"(b));
    return d;
}
__device__ __forceinline__ float tanh_approx(float x) {
    float y;
    asm("tanh.approx.f32 %0, %1;" : "=f"(y) : "f"(x));
    return y;
}
__device__ __forceinline__ float to_tf32(float x) {
    float y;
    asm("cvt.rna.tf32.f32 %0, %1;" : "=f"(y) : "f"(x));
    return y;
}
__device__ __forceinline__ unsigned ld_acq(const unsigned* p) {
    unsigned v;
    asm volatile("ld.acquire.gpu.global.u32 %0, [%1];" : "=r"(v) : "l"(p));
    return v;
}
__device__ __forceinline__ void st_rel(unsigned* p, unsigned v) {
    asm volatile("st.release.gpu.global.u32 [%0], %1;" :: "l"(p), "r"(v) : "memory");
}
__device__ __forceinline__ void mma_tf32(float* d, const unsigned* a,
                                         unsigned b0, unsigned b1) {
    asm volatile(
        "mma.sync.aligned.m16n8k8.row.col.f32.tf32.tf32.f32 "
        "{%0,%1,%2,%3}, {%4,%5,%6,%7}, {%8,%9}, {%0,%1,%2,%3};"
        : "+f"(d[0]), "+f"(d[1]), "+f"(d[2]), "+f"(d[3])
        : "r"(a[0]), "r"(a[1]), "r"(a[2]), "r"(a[3]), "r"(b0), "r"(b1));
}

// ---------------- prep: rowsums of Wr and W ----------------------------------
__global__ void prep_kernel(const float* __restrict__ Wr, const float* __restrict__ W)
{
    int warp = threadIdx.x >> 5, lane = threadIdx.x & 31;
    int rowId = blockIdx.x * 8 + warp;               // 0..1023
    const float* src = (rowId < HH) ? Wr : W;
    int h = rowId & (HH - 1);
    const float4* s4 = reinterpret_cast<const float4*>(src + (size_t)h * HH);
    float s = 0.f;
    for (int i = lane; i < HH / 4; i += 32) {
        float4 v = s4[i];
        s += (v.x + v.y) + (v.z + v.w);
    }
#pragma unroll
    for (int o = 16; o > 0; o >>= 1) s += __shfl_xor_sync(0xffffffffu, s, o);
    if (lane == 0) {
        if (rowId < HH) g_rsWr[h] = s;
        else            g_rsW[h]  = s;
    }
}

// ---------------- gate MLP: tf32 mma.sync + fused z-build + tanh + z2 dot -----
// grid (S/128, 512/128, B), 256 threads = 8 warps (4 s x 2 j). (R11 version.)
__global__ void __launch_bounds__(256, 2) gate_kernel(
    const float* __restrict__ facts, const float* __restrict__ q,
    const float* __restrict__ m, const float* __restrict__ z1w,
    const float* __restrict__ z1b, const float* __restrict__ z2w)
{
    extern __shared__ __align__(16) float gsm[];
    float* As   = gsm;                   // [4][16][132] tf32 z-variants (k-major)
    float* Bs   = As + 4 * 16 * 132;     // [4][16][132] tf32 z1w tile (k-major)
    float* qs   = Bs + 4 * 16 * 132;     // [512]
    float* ms   = qs + HH;               // [512]
    float* z1bs = ms + HH;               // [128]
    float* z2ws = z1bs + 128;            // [128]
    float* ps   = z2ws + 128;            // [8][32] per-warp s-partials

    int tid = threadIdx.x;
    int b  = blockIdx.z;
    int s0 = blockIdx.x * 128;
    int j0 = blockIdx.y * 128;
    int wid = tid >> 5, lane = tid & 31;
    int ws = wid >> 1, wj = wid & 1;      // warp grid 4(s) x 2(j)
    int gp = lane >> 2, tg = lane & 3;    // mma group / thread-in-group

    for (int i = tid; i < HH; i += 256) {
        qs[i] = q[b * HH + i];
        ms[i] = m[b * HH + i];
    }
    if (tid < 128) {
        z1bs[tid] = z1b[j0 + tid];
        z2ws[tid] = z2w[j0 + tid];
    }

    const float* fb = facts + ((size_t)b * SS + s0) * HH;

    float acc[2][8][4];                   // [s-subtile][j-subtile][frag]
#pragma unroll
    for (int i = 0; i < 2; i++)
#pragma unroll
        for (int j = 0; j < 8; j++)
#pragma unroll
            for (int k = 0; k < 4; k++) acc[i][j][k] = 0.f;

    for (int c = 0; c < 32; c++) {        // 32 chunks of 16 facts-k
        int k0 = c * 16;
        __syncthreads();                  // prev compute done (covers qs/ms @c=0)

        // build As: 4 tf32 z-variants of the facts k-chunk
#pragma unroll
        for (int r = 0; r < 8; r++) {
            int idx = tid + r * 256;
            int ss = idx >> 4, kk = idx & 15;
            float fv = fb[(size_t)ss * HH + k0 + kk];
            float qv = qs[k0 + kk], mv = ms[k0 + kk];
            As[(0 * 16 + kk) * 132 + ss] = to_tf32(fv * qv);
            As[(1 * 16 + kk) * 132 + ss] = to_tf32(fv * mv);
            As[(2 * 16 + kk) * 132 + ss] = to_tf32(fabsf(fv - qv));
            As[(3 * 16 + kk) * 132 + ss] = to_tf32(fabsf(fv - mv));
        }
        // stage Bs: z1w rows {v*512 + k0 + kk}, cols j0..j0+127, as tf32
#pragma unroll
        for (int r = 0; r < 8; r++) {
            int idx = tid + r * 256;        // float4 index 0..2047
            int row = idx >> 5;             // 0..63: v = row>>4, kk = row&15
            int c4 = idx & 31;
            float4 v4 = *reinterpret_cast<const float4*>(
                &z1w[(size_t)((row >> 4) * HH + k0 + (row & 15)) * HH + j0 + c4 * 4]);
            float* dst = &Bs[row * 132 + c4 * 4];
            dst[0] = to_tf32(v4.x); dst[1] = to_tf32(v4.y);
            dst[2] = to_tf32(v4.z); dst[3] = to_tf32(v4.w);
        }
        __syncthreads();                  // As/Bs ready

        // compute: 4 variants x 2 k8-substeps
#pragma unroll
        for (int sub = 0; sub < 8; sub++) {
            int v = sub >> 1, k8 = (sub & 1) * 8;
            const float* Av = &As[v * 16 * 132];
            const float* Bv = &Bs[v * 16 * 132];
            unsigned a[2][4];
#pragma unroll
            for (int st = 0; st < 2; st++) {
                int row0 = ws * 32 + st * 16 + gp;
                a[st][0] = __float_as_uint(Av[(k8 + tg) * 132 + row0]);
                a[st][1] = __float_as_uint(Av[(k8 + tg) * 132 + row0 + 8]);
                a[st][2] = __float_as_uint(Av[(k8 + tg + 4) * 132 + row0]);
                a[st][3] = __float_as_uint(Av[(k8 + tg + 4) * 132 + row0 + 8]);
            }
#pragma unroll
            for (int jt = 0; jt < 8; jt++) {
                int n0 = wj * 64 + jt * 8 + gp;
                unsigned b0 = __float_as_uint(Bv[(k8 + tg) * 132 + n0]);
                unsigned b1 = __float_as_uint(Bv[(k8 + tg + 4) * 132 + n0]);
                mma_tf32(acc[0][jt], a[0], b0, b1);
                mma_tf32(acc[1][jt], a[1], b0, b1);
            }
        }
    }

    // epilogue: tanh(acc + z1b) . z2w, reduce over this block's 128 j
#pragma unroll
    for (int st = 0; st < 2; st++) {
        float s_r0 = 0.f, s_r1 = 0.f;
#pragma unroll
        for (int jt = 0; jt < 8; jt++) {
#pragma unroll
            for (int ci = 0; ci < 2; ci++) {
                int col = wj * 64 + jt * 8 + tg * 2 + ci;
                float zb = z1bs[col], zw = z2ws[col];
                s_r0 = fmaf(tanh_approx(acc[st][jt][ci] + zb), zw, s_r0);
                s_r1 = fmaf(tanh_approx(acc[st][jt][2 + ci] + zb), zw, s_r1);
            }
        }
#pragma unroll
        for (int o = 1; o <= 2; o <<= 1) {
            s_r0 += __shfl_xor_sync(0xffffffffu, s_r0, o);
            s_r1 += __shfl_xor_sync(0xffffffffu, s_r1, o);
        }
        if (tg == 0) {
            ps[wid * 32 + st * 16 + gp]     = s_r0;
            ps[wid * 32 + st * 16 + 8 + gp] = s_r1;
        }
    }
    __syncthreads();
    if (tid < 128) {
        int wsx = tid >> 5, wi = tid & 31;
        float v = ps[(wsx * 2 + 0) * 32 + wi] + ps[(wsx * 2 + 1) * 32 + wi];
        g_part[blockIdx.y][b * SS + s0 + tid] = v;
    }
}

// ---------------- softmax over S per batch (also zeroes scan flags) -----------
__global__ void softmax_kernel()
{
    int b = blockIdx.x, s = threadIdx.x;   // 256 threads
    if (b == 0 && s < 128) g_flagp[s >> 4][s & 15][0] = 0u;  // zero flag words
    float l = 0.f;
#pragma unroll
    for (int jb = 0; jb < 4; jb++) l += g_part[jb][b * SS + s];
    __shared__ float sm[256];
    sm[s] = l;
    __syncthreads();
#pragma unroll
    for (int o = 128; o > 0; o >>= 1) {
        if (s < o) sm[s] = fmaxf(sm[s], sm[s + o]);
        __syncthreads();
    }
    float mx = sm[0];
    __syncthreads();
    float e = expf(l - mx);
    sm[s] = e;
    __syncthreads();
#pragma unroll
    for (int o = 128; o > 0; o >>= 1) {
        if (s < o) sm[s] += sm[s + o];
        __syncthreads();
    }
    g_Gt[s * BB + b] = e / sm[0];
}

// ---------------- persistent scan: 128 blocks = 16 hg x 8 bg ------------------
// Dataflow sync: consumer warp ks reads C rows [ks*32, ks*32+32), produced by
// exactly block (hg=ks, bg). Each warp polls only its own producer's flag ->
// producer skew is absorbed instead of stacked. Single producer per flag word
// (st.release, no atomics), 128B padded.
__global__ void __launch_bounds__(512, 1) scan_persist(
    const float* __restrict__ facts,
    const float* __restrict__ Ur, const float* __restrict__ U,
    const float* __restrict__ br, const float* __restrict__ bur,
    const float* __restrict__ bw, const float* __restrict__ bu)
{
    extern __shared__ __align__(16) char dsm[];
    u64* wpk = reinterpret_cast<u64*>(dsm);            // [512][32]: pk2(Ur, U)
    u64* red = reinterpret_cast<u64*>(dsm + 131072);   // [16][16][33] padded

    __shared__ float hcs[5][32];

    int tid = threadIdx.x;
    int hg = blockIdx.x >> 3;      // 0..15
    int bg = blockIdx.x & 7;       // 0..7
    int h0 = hg * 32;
    int b0 = bg * 16;

    // one-time: pack (R,U) weight pairs for this h-slice
    for (int idx = tid; idx < 512 * 32; idx += 512) {
        int k = idx >> 5, h = idx & 31;
        wpk[idx] = pk2(Ur[(size_t)k * HH + h0 + h], U[(size_t)k * HH + h0 + h]);
    }
    if (tid < 32) {
        int h = h0 + tid;
        hcs[0][tid] = g_rsWr[h];
        hcs[1][tid] = br[h] + bur[h];
        hcs[2][tid] = g_rsW[h];
        hcs[3][tid] = bw[h];
        hcs[4][tid] = bu[h];
    }
    __syncthreads();

    // compute mapping: warp ks consumes producer hg=ks's C slice
    int ks = tid >> 5;
    int lane = tid & 31;
    int hq = lane >> 2, bq = lane & 3;

    // reduce/epilogue mapping: one (h,b) per thread, fixed across steps
    int ep_pos = tid >> 4, ep_i = tid & 15;
    int e_hq = ep_pos >> 2, e_bq = ep_pos & 3;
    int e_hh = ep_i & 3,   e_bb = ep_i >> 2;        // hh fastest -> coalesced facts
    int ehl = e_hq * 4 + e_hh;                      // local h
    int eh  = h0 + ehl;
    int eb  = b0 + e_bq * 4 + e_bb;
    float cur_c = 0.f;

    unsigned* myflag   = &g_flagp[bg][hg][0];       // this block's producer flag
    const unsigned* srcflag = &g_flagp[bg][ks][0];  // this warp's producer flag

    for (int s = 0; s < SS; s++) {
        u64 aRU = 0ull;

        if (s > 0) {
            // per-warp poll: only MY producer (hg=ks) must have finished s-1
            if (lane == 0) {
                while (ld_acq(srcflag) < (unsigned)s) {}
            }
            __syncwarp();   // extend lane0's acquire to the whole warp

            const float* __restrict__ Cin = g_C[s & 1];
            u64 acc[4][4];
#pragma unroll
            for (int i = 0; i < 4; i++)
#pragma unroll
                for (int j = 0; j < 4; j++) acc[i][j] = 0ull;

            const float4* cp = reinterpret_cast<const float4*>(
                Cin + (size_t)(ks * 32) * BB + b0 + bq * 4);
#pragma unroll 4
            for (int kk = 0; kk < 32; kk++) {
                float4 cv = __ldcg(cp + (size_t)kk * (BB / 4));
                u64 cd[4] = {pk2(cv.x, cv.x), pk2(cv.y, cv.y),
                             pk2(cv.z, cv.z), pk2(cv.w, cv.w)};
                const u64* wr = &wpk[(ks * 32 + kk) * 32 + hq * 4];
                ulonglong2 w01 = *reinterpret_cast<const ulonglong2*>(wr);
                ulonglong2 w23 = *reinterpret_cast<const ulonglong2*>(wr + 2);
                u64 w[4] = {w01.x, w01.y, w23.x, w23.y};
#pragma unroll
                for (int hh = 0; hh < 4; hh++)
#pragma unroll
                    for (int bb = 0; bb < 4; bb++)
                        acc[hh][bb] = fma2_(cd[bb], w[hh], acc[hh][bb]);
            }

            // write k-split partials (prev step's red reads sealed by last sync)
#pragma unroll
            for (int hh = 0; hh < 4; hh++)
#pragma unroll
                for (int bb = 0; bb < 4; bb++) {
                    int i = bb * 4 + hh;
                    red[(size_t)(ks * 16 + i) * 33 + lane] = acc[hh][bb];
                }
            __syncthreads();

            // each thread sums its 16 k-split partials for its own (h,b)
            u64 v = red[(size_t)ep_i * 33 + ep_pos];
#pragma unroll
            for (int t = 1; t < 16; t++)
                v = add2_(v, red[(size_t)(t * 16 + ep_i) * 33 + ep_pos]);
            aRU = v;
        }

        // fused epilogue: nonlinearity + blend; C kept in a register
        {
            float aR, aU;
            upk2(aRU, aR, aU);
            float* __restrict__ Cout = g_C[(s + 1) & 1];
            float fv = __ldg(facts + ((size_t)eb * SS + s) * HH + eh);
            float g = g_Gt[s * BB + eb];
            float rr = 1.f / (1.f + expf(-(fmaf(fv, hcs[0][ehl], hcs[1][ehl]) + aR)));
            float ht = tanhf(fmaf(rr, aU + hcs[4][ehl],
                                  fmaf(fv, hcs[2][ehl], hcs[3][ehl])));
            cur_c = fmaf(g, ht - cur_c, cur_c);
            __stcg(&Cout[(size_t)eh * BB + eb], cur_c);
        }
        __syncthreads();       // all C stores in this block issued (program order)
        // single-producer release store: orders this block's C stores (via the
        // syncthreads hb) before the flag value consumers acquire.
        if (tid == 0) st_rel(myflag, (unsigned)(s + 1));
    }
}

// ---------------- final: relu(concat @ nm_w + nm_b) ---------------------------
__global__ void __launch_bounds__(512) final_kernel(
    const float* __restrict__ prevM, const float* __restrict__ q,
    const float* __restrict__ nm_w, const float* __restrict__ nm_b,
    float* __restrict__ out)
{
    __shared__ float cs[3 * HH];
    int b = blockIdx.x, tid = threadIdx.x;    // 512 threads
    cs[tid]          = prevM[b * HH + tid];
    cs[HH + tid]     = g_C[0][(size_t)tid * BB + b];   // final C lives in buffer 0
    cs[2 * HH + tid] = q[b * HH + tid];
    __syncthreads();
    float acc = nm_b[tid];
#pragma unroll 8
    for (int k = 0; k < 3 * HH; k++)
        acc = fmaf(cs[k], nm_w[(size_t)k * HH + tid], acc);
    out[b * HH + tid] = fmaxf(acc, 0.f);
}

// ---------------- launch -------------------------------------------------------
extern "C" void kernel_launch(void* const* d_in, const int* in_sizes, int n_in,
                              void* d_out, int out_size)
{
    const float* facts     = (const float*)d_in[0];
    const float* questions = (const float*)d_in[1];
    const float* prevM     = (const float*)d_in[2];
    const float* z1_w      = (const float*)d_in[3];
    const float* z1_b      = (const float*)d_in[4];
    const float* z2_w      = (const float*)d_in[5];
    // d_in[6] z2_b: constant shift, softmax-invariant — unused
    const float* Wr        = (const float*)d_in[7];
    const float* br        = (const float*)d_in[8];
    const float* Ur        = (const float*)d_in[9];
    const float* bur       = (const float*)d_in[10];
    const float* W         = (const float*)d_in[11];
    const float* bw        = (const float*)d_in[12];
    const float* U         = (const float*)d_in[13];
    const float* bu        = (const float*)d_in[14];
    const float* nm_w      = (const float*)d_in[15];
    const float* nm_b      = (const float*)d_in[16];
    float* out = (float*)d_out;

    const int scan_smem = 131072 + 16 * 16 * 33 * 8;   // wpk + red = 198656
    cudaFuncSetAttribute(scan_persist,
                         cudaFuncAttributeMaxDynamicSharedMemorySize, scan_smem);
    const int gate_smem = (2 * 4 * 16 * 132 + 2 * HH + 2 * 128 + 256) * 4; // 73728
    cudaFuncSetAttribute(gate_kernel,
                         cudaFuncAttributeMaxDynamicSharedMemorySize, gate_smem);

    prep_kernel<<<128, 256>>>(Wr, W);
    gate_kernel<<<dim3(2, 4, BB), 256, gate_smem>>>(facts, questions, prevM,
                                                    z1_w, z1_b, z2_w);
    softmax_kernel<<<BB, 256>>>();
    scan_persist<<<128, 512, scan_smem>>>(facts, Ur, U, br, bur, bw, bu);
    final_kernel<<<BB, 512>>>(prevM, questions, nm_w, nm_b, out);
}

// round 15
// speedup vs baseline: 1.4477x; 1.1652x over previous
#include <cuda_runtime.h>
#include <math.h>

#define BB 128
#define SS 256
#define HH 512

typedef unsigned long long u64;

// ---------------- device scratch (no allocations allowed) -------------------
__device__ float g_rsWr[HH];            // rowsum(Wr)
__device__ float g_rsW[HH];             // rowsum(W)
__device__ float g_part[4][BB * SS];    // per-jblock logit partials
__device__ float g_Gt[SS * BB];         // softmax gates, (s, b)
__device__ float g_C[2][HH * BB];       // recurrent state, transposed (h, b)
__device__ unsigned g_flagp[8][16][32]; // per-(bg,hg) step flag, 128B padded

// ---------------- f32x2 / misc helpers ----------------------------------------
__device__ __forceinline__ u64 pk2(float x, float y) {
    u64 r;
    asm("mov.b64 %0, {%1,%2};" : "=l"(r) : "f"(x), "f"(y));
    return r;
}
__device__ __forceinline__ void upk2(u64 v, float& x, float& y) {
    asm("mov.b64 {%0,%1}, %2;" : "=f"(x), "=f"(y) : "l"(v));
}
__device__ __forceinline__ u64 fma2_(u64 a, u64 b, u64 c) {
    u64 d;
    asm("fma.rn.f32x2 %0, %1, %2, %3;" : "=l"(d) : "l"(a), "l"(b), "l"(c));
    return d;
}
__device__ __forceinline__ u64 add2_(u64 a, u64 b) {
    u64 d;
    asm("add.rn.f32x2 %0, %1, %2;" : "=l"(d) : "l"(a), "l"(b));
    return d;
}
__device__ __forceinline__ float tanh_approx(float x) {
    float y;
    asm("tanh.approx.f32 %0, %1;" : "=f"(y) : "f"(x));
    return y;
}
// pack two floats to bf16x2: lo -> low half, hi -> high half
__device__ __forceinline__ unsigned pkbf2(float lo, float hi) {
    unsigned r;
    asm("cvt.rn.bf16x2.f32 %0, %1, %2;" : "=r"(r) : "f"(hi), "f"(lo));
    return r;
}
__device__ __forceinline__ unsigned ld_acq(const unsigned* p) {
    unsigned v;
    asm volatile("ld.acquire.gpu.global.u32 %0, [%1];" : "=r"(v) : "l"(p));
    return v;
}
__device__ __forceinline__ void st_rel(unsigned* p, unsigned v) {
    asm volatile("st.release.gpu.global.u32 [%0], %1;" :: "l"(p), "r"(v) : "memory");
}
__device__ __forceinline__ void mma_bf16(float* d, const unsigned* a,
                                         unsigned b0, unsigned b1) {
    asm volatile(
        "mma.sync.aligned.m16n8k16.row.col.f32.bf16.bf16.f32 "
        "{%0,%1,%2,%3}, {%4,%5,%6,%7}, {%8,%9}, {%0,%1,%2,%3};"
        : "+f"(d[0]), "+f"(d[1]), "+f"(d[2]), "+f"(d[3])
        : "r"(a[0]), "r"(a[1]), "r"(a[2]), "r"(a[3]), "r"(b0), "r"(b1));
}

// ---------------- prep: rowsums of Wr and W ----------------------------------
__global__ void prep_kernel(const float* __restrict__ Wr, const float* __restrict__ W)
{
    int warp = threadIdx.x >> 5, lane = threadIdx.x & 31;
    int rowId = blockIdx.x * 8 + warp;               // 0..1023
    const float* src = (rowId < HH) ? Wr : W;
    int h = rowId & (HH - 1);
    const float4* s4 = reinterpret_cast<const float4*>(src + (size_t)h * HH);
    float s = 0.f;
    for (int i = lane; i < HH / 4; i += 32) {
        float4 v = s4[i];
        s += (v.x + v.y) + (v.z + v.w);
    }
#pragma unroll
    for (int o = 16; o > 0; o >>= 1) s += __shfl_xor_sync(0xffffffffu, s, o);
    if (lane == 0) {
        if (rowId < HH) g_rsWr[h] = s;
        else            g_rsW[h]  = s;
    }
}

// ---------------- gate MLP: bf16 mma.sync (m16n8k16) + fused z-build ----------
// grid (S/128, 512/128, B), 256 threads = 8 warps (4 s x 2 j).
// z built on the fly as bf16x2 k-pairs; As32/Bs32: [4][8][136] u32, kk2-major.
__global__ void __launch_bounds__(256, 2) gate_kernel(
    const float* __restrict__ facts, const float* __restrict__ q,
    const float* __restrict__ m, const float* __restrict__ z1w,
    const float* __restrict__ z1b, const float* __restrict__ z2w)
{
    extern __shared__ __align__(16) unsigned gsm_u[];
    unsigned* As32 = gsm_u;                 // [4][8][136] bf16x2 z-variants
    unsigned* Bs32 = As32 + 4 * 8 * 136;    // [4][8][136] bf16x2 z1w tile
    float* qs   = reinterpret_cast<float*>(Bs32 + 4 * 8 * 136);  // [512]
    float* ms   = qs + HH;                  // [512]
    float* z1bs = ms + HH;                  // [128]
    float* z2ws = z1bs + 128;               // [128]
    float* ps   = z2ws + 128;               // [8][32] per-warp s-partials

    int tid = threadIdx.x;
    int b  = blockIdx.z;
    int s0 = blockIdx.x * 128;
    int j0 = blockIdx.y * 128;
    int wid = tid >> 5, lane = tid & 31;
    int ws = wid >> 1, wj = wid & 1;      // warp grid 4(s) x 2(j)
    int gp = lane >> 2, tg = lane & 3;    // mma group / thread-in-group

    for (int i = tid; i < HH; i += 256) {
        qs[i] = q[b * HH + i];
        ms[i] = m[b * HH + i];
    }
    if (tid < 128) {
        z1bs[tid] = z1b[j0 + tid];
        z2ws[tid] = z2w[j0 + tid];
    }

    const float* fb = facts + ((size_t)b * SS + s0) * HH;

    float acc[2][8][4];                   // [s-subtile][j-subtile][frag]
#pragma unroll
    for (int i = 0; i < 2; i++)
#pragma unroll
        for (int j = 0; j < 8; j++)
#pragma unroll
            for (int k = 0; k < 4; k++) acc[i][j][k] = 0.f;

    for (int c = 0; c < 32; c++) {        // 32 chunks of 16 facts-k
        int k0 = c * 16;
        __syncthreads();                  // prev compute done (covers qs/ms @c=0)

        // build As32: 4 bf16x2 z-variants; idx -> (ss 0..127, kk2 0..7)
#pragma unroll
        for (int r = 0; r < 4; r++) {
            int idx = tid + r * 256;
            int ss = idx >> 3, kk2 = idx & 7;
            float2 fv = *reinterpret_cast<const float2*>(
                &fb[(size_t)ss * HH + k0 + 2 * kk2]);
            float2 qv = *reinterpret_cast<const float2*>(&qs[k0 + 2 * kk2]);
            float2 mv = *reinterpret_cast<const float2*>(&ms[k0 + 2 * kk2]);
            int base = kk2 * 136 + ss;
            As32[0 * 8 * 136 + base] = pkbf2(fv.x * qv.x, fv.y * qv.y);
            As32[1 * 8 * 136 + base] = pkbf2(fv.x * mv.x, fv.y * mv.y);
            As32[2 * 8 * 136 + base] = pkbf2(fabsf(fv.x - qv.x), fabsf(fv.y - qv.y));
            As32[3 * 8 * 136 + base] = pkbf2(fabsf(fv.x - mv.x), fabsf(fv.y - mv.y));
        }
        // stage Bs32: rows (v,kk2) pack z1w rows k0+2kk2 (lo) and +1 (hi)
#pragma unroll
        for (int r = 0; r < 4; r++) {
            int idx = tid + r * 256;        // 0..1023
            int row = idx >> 5;             // 0..31: v = row>>3, kk2 = row&7
            int jj4 = idx & 31;             // float4 col group
            size_t rA = (size_t)((row >> 3) * HH + k0 + 2 * (row & 7)) * HH + j0 + jj4 * 4;
            float4 a4 = *reinterpret_cast<const float4*>(&z1w[rA]);
            float4 b4 = *reinterpret_cast<const float4*>(&z1w[rA + HH]);
            unsigned* dst = &Bs32[row * 136 + jj4 * 4];
            dst[0] = pkbf2(a4.x, b4.x);
            dst[1] = pkbf2(a4.y, b4.y);
            dst[2] = pkbf2(a4.z, b4.z);
            dst[3] = pkbf2(a4.w, b4.w);
        }
        __syncthreads();                  // As/Bs ready

        // compute: 4 variants, one k16 mma-step each
#pragma unroll
        for (int v = 0; v < 4; v++) {
            const unsigned* Av = &As32[v * 8 * 136];
            const unsigned* Bv = &Bs32[v * 8 * 136];
            unsigned a[2][4];
#pragma unroll
            for (int st = 0; st < 2; st++) {
                int row0 = ws * 32 + st * 16 + gp;
                a[st][0] = Av[tg * 136 + row0];
                a[st][1] = Av[tg * 136 + row0 + 8];
                a[st][2] = Av[(tg + 4) * 136 + row0];
                a[st][3] = Av[(tg + 4) * 136 + row0 + 8];
            }
#pragma unroll
            for (int jt = 0; jt < 8; jt++) {
                int n0 = wj * 64 + jt * 8 + gp;
                unsigned b0 = Bv[tg * 136 + n0];
                unsigned b1 = Bv[(tg + 4) * 136 + n0];
                mma_bf16(acc[0][jt], a[0], b0, b1);
                mma_bf16(acc[1][jt], a[1], b0, b1);
            }
        }
    }

    // epilogue: tanh(acc + z1b) . z2w, reduce over this block's 128 j
#pragma unroll
    for (int st = 0; st < 2; st++) {
        float s_r0 = 0.f, s_r1 = 0.f;
#pragma unroll
        for (int jt = 0; jt < 8; jt++) {
#pragma unroll
            for (int ci = 0; ci < 2; ci++) {
                int col = wj * 64 + jt * 8 + tg * 2 + ci;
                float zb = z1bs[col], zw = z2ws[col];
                s_r0 = fmaf(tanh_approx(acc[st][jt][ci] + zb), zw, s_r0);
                s_r1 = fmaf(tanh_approx(acc[st][jt][2 + ci] + zb), zw, s_r1);
            }
        }
#pragma unroll
        for (int o = 1; o <= 2; o <<= 1) {
            s_r0 += __shfl_xor_sync(0xffffffffu, s_r0, o);
            s_r1 += __shfl_xor_sync(0xffffffffu, s_r1, o);
        }
        if (tg == 0) {
            ps[wid * 32 + st * 16 + gp]     = s_r0;
            ps[wid * 32 + st * 16 + 8 + gp] = s_r1;
        }
    }
    __syncthreads();
    if (tid < 128) {
        int wsx = tid >> 5, wi = tid & 31;
        float v = ps[(wsx * 2 + 0) * 32 + wi] + ps[(wsx * 2 + 1) * 32 + wi];
        g_part[blockIdx.y][b * SS + s0 + tid] = v;
    }
}

// ---------------- softmax over S per batch (also zeroes scan flags) -----------
__global__ void softmax_kernel()
{
    int b = blockIdx.x, s = threadIdx.x;   // 256 threads
    if (b == 0 && s < 128) g_flagp[s >> 4][s & 15][0] = 0u;  // zero flag words
    float l = 0.f;
#pragma unroll
    for (int jb = 0; jb < 4; jb++) l += g_part[jb][b * SS + s];
    __shared__ float sm[256];
    sm[s] = l;
    __syncthreads();
#pragma unroll
    for (int o = 128; o > 0; o >>= 1) {
        if (s < o) sm[s] = fmaxf(sm[s], sm[s + o]);
        __syncthreads();
    }
    float mx = sm[0];
    __syncthreads();
    float e = expf(l - mx);
    sm[s] = e;
    __syncthreads();
#pragma unroll
    for (int o = 128; o > 0; o >>= 1) {
        if (s < o) sm[s] += sm[s + o];
        __syncthreads();
    }
    g_Gt[s * BB + b] = e / sm[0];
}

// ---------------- persistent scan: 128 blocks = 16 hg x 8 bg (R13 verbatim) ---
__global__ void __launch_bounds__(512, 1) scan_persist(
    const float* __restrict__ facts,
    const float* __restrict__ Ur, const float* __restrict__ U,
    const float* __restrict__ br, const float* __restrict__ bur,
    const float* __restrict__ bw, const float* __restrict__ bu)
{
    extern __shared__ __align__(16) char dsm[];
    u64* wpk = reinterpret_cast<u64*>(dsm);            // [512][32]: pk2(Ur, U)
    u64* red = reinterpret_cast<u64*>(dsm + 131072);   // [16][16][33] padded

    __shared__ float hcs[5][32];

    int tid = threadIdx.x;
    int hg = blockIdx.x >> 3;      // 0..15
    int bg = blockIdx.x & 7;       // 0..7
    int h0 = hg * 32;
    int b0 = bg * 16;

    // one-time: pack (R,U) weight pairs for this h-slice
    for (int idx = tid; idx < 512 * 32; idx += 512) {
        int k = idx >> 5, h = idx & 31;
        wpk[idx] = pk2(Ur[(size_t)k * HH + h0 + h], U[(size_t)k * HH + h0 + h]);
    }
    if (tid < 32) {
        int h = h0 + tid;
        hcs[0][tid] = g_rsWr[h];
        hcs[1][tid] = br[h] + bur[h];
        hcs[2][tid] = g_rsW[h];
        hcs[3][tid] = bw[h];
        hcs[4][tid] = bu[h];
    }
    __syncthreads();

    // compute mapping: warp ks consumes producer hg=ks's C slice
    int ks = tid >> 5;
    int lane = tid & 31;
    int hq = lane >> 2, bq = lane & 3;

    // reduce/epilogue mapping: one (h,b) per thread, fixed across steps
    int ep_pos = tid >> 4, ep_i = tid & 15;
    int e_hq = ep_pos >> 2, e_bq = ep_pos & 3;
    int e_hh = ep_i & 3,   e_bb = ep_i >> 2;        // hh fastest -> coalesced facts
    int ehl = e_hq * 4 + e_hh;                      // local h
    int eh  = h0 + ehl;
    int eb  = b0 + e_bq * 4 + e_bb;
    float cur_c = 0.f;

    unsigned* myflag   = &g_flagp[bg][hg][0];       // this block's producer flag
    const unsigned* srcflag = &g_flagp[bg][ks][0];  // this warp's producer flag

    for (int s = 0; s < SS; s++) {
        u64 aRU = 0ull;

        if (s > 0) {
            // per-warp poll: only MY producer (hg=ks) must have finished s-1
            if (lane == 0) {
                while (ld_acq(srcflag) < (unsigned)s) {}
            }
            __syncwarp();   // extend lane0's acquire to the whole warp

            const float* __restrict__ Cin = g_C[s & 1];
            u64 acc[4][4];
#pragma unroll
            for (int i = 0; i < 4; i++)
#pragma unroll
                for (int j = 0; j < 4; j++) acc[i][j] = 0ull;

            const float4* cp = reinterpret_cast<const float4*>(
                Cin + (size_t)(ks * 32) * BB + b0 + bq * 4);
#pragma unroll 4
            for (int kk = 0; kk < 32; kk++) {
                float4 cv = __ldcg(cp + (size_t)kk * (BB / 4));
                u64 cd[4] = {pk2(cv.x, cv.x), pk2(cv.y, cv.y),
                             pk2(cv.z, cv.z), pk2(cv.w, cv.w)};
                const u64* wr = &wpk[(ks * 32 + kk) * 32 + hq * 4];
                ulonglong2 w01 = *reinterpret_cast<const ulonglong2*>(wr);
                ulonglong2 w23 = *reinterpret_cast<const ulonglong2*>(wr + 2);
                u64 w[4] = {w01.x, w01.y, w23.x, w23.y};
#pragma unroll
                for (int hh = 0; hh < 4; hh++)
#pragma unroll
                    for (int bb = 0; bb < 4; bb++)
                        acc[hh][bb] = fma2_(cd[bb], w[hh], acc[hh][bb]);
            }

            // write k-split partials (prev step's red reads sealed by last sync)
#pragma unroll
            for (int hh = 0; hh < 4; hh++)
#pragma unroll
                for (int bb = 0; bb < 4; bb++) {
                    int i = bb * 4 + hh;
                    red[(size_t)(ks * 16 + i) * 33 + lane] = acc[hh][bb];
                }
            __syncthreads();

            // each thread sums its 16 k-split partials for its own (h,b)
            u64 v = red[(size_t)ep_i * 33 + ep_pos];
#pragma unroll
            for (int t = 1; t < 16; t++)
                v = add2_(v, red[(size_t)(t * 16 + ep_i) * 33 + ep_pos]);
            aRU = v;
        }

        // fused epilogue: nonlinearity + blend; C kept in a register
        {
            float aR, aU;
            upk2(aRU, aR, aU);
            float* __restrict__ Cout = g_C[(s + 1) & 1];
            float fv = __ldg(facts + ((size_t)eb * SS + s) * HH + eh);
            float g = g_Gt[s * BB + eb];
            float rr = 1.f / (1.f + expf(-(fmaf(fv, hcs[0][ehl], hcs[1][ehl]) + aR)));
            float ht = tanhf(fmaf(rr, aU + hcs[4][ehl],
                                  fmaf(fv, hcs[2][ehl], hcs[3][ehl])));
            cur_c = fmaf(g, ht - cur_c, cur_c);
            __stcg(&Cout[(size_t)eh * BB + eb], cur_c);
        }
        __syncthreads();       // all C stores in this block issued (program order)
        if (tid == 0) st_rel(myflag, (unsigned)(s + 1));
    }
}

// ---------------- final: relu(concat @ nm_w + nm_b) ---------------------------
__global__ void __launch_bounds__(512) final_kernel(
    const float* __restrict__ prevM, const float* __restrict__ q,
    const float* __restrict__ nm_w, const float* __restrict__ nm_b,
    float* __restrict__ out)
{
    __shared__ float cs[3 * HH];
    int b = blockIdx.x, tid = threadIdx.x;    // 512 threads
    cs[tid]          = prevM[b * HH + tid];
    cs[HH + tid]     = g_C[0][(size_t)tid * BB + b];   // final C lives in buffer 0
    cs[2 * HH + tid] = q[b * HH + tid];
    __syncthreads();
    float acc = nm_b[tid];
#pragma unroll 8
    for (int k = 0; k < 3 * HH; k++)
        acc = fmaf(cs[k], nm_w[(size_t)k * HH + tid], acc);
    out[b * HH + tid] = fmaxf(acc, 0.f);
}

// ---------------- launch -------------------------------------------------------
extern "C" void kernel_launch(void* const* d_in, const int* in_sizes, int n_in,
                              void* d_out, int out_size)
{
    const float* facts     = (const float*)d_in[0];
    const float* questions = (const float*)d_in[1];
    const float* prevM     = (const float*)d_in[2];
    const float* z1_w      = (const float*)d_in[3];
    const float* z1_b      = (const float*)d_in[4];
    const float* z2_w      = (const float*)d_in[5];
    // d_in[6] z2_b: constant shift, softmax-invariant — unused
    const float* Wr        = (const float*)d_in[7];
    const float* br        = (const float*)d_in[8];
    const float* Ur        = (const float*)d_in[9];
    const float* bur       = (const float*)d_in[10];
    const float* W         = (const float*)d_in[11];
    const float* bw        = (const float*)d_in[12];
    const float* U         = (const float*)d_in[13];
    const float* bu        = (const float*)d_in[14];
    const float* nm_w      = (const float*)d_in[15];
    const float* nm_b      = (const float*)d_in[16];
    float* out = (float*)d_out;

    const int scan_smem = 131072 + 16 * 16 * 33 * 8;   // wpk + red = 198656
    cudaFuncSetAttribute(scan_persist,
                         cudaFuncAttributeMaxDynamicSharedMemorySize, scan_smem);
    const int gate_smem = (2 * 4 * 8 * 136 + 2 * HH + 2 * 128 + 256) * 4; // 40960
    cudaFuncSetAttribute(gate_kernel,
                         cudaFuncAttributeMaxDynamicSharedMemorySize, gate_smem);

    prep_kernel<<<128, 256>>>(Wr, W);
    gate_kernel<<<dim3(2, 4, BB), 256, gate_smem>>>(facts, questions, prevM,
                                                    z1_w, z1_b, z2_w);
    softmax_kernel<<<BB, 256>>>();
    scan_persist<<<128, 512, scan_smem>>>(facts, Ur, U, br, bur, bw, bu);
    final_kernel<<<BB, 512>>>(prevM, questions, nm_w, nm_b, out);
}

// round 16
// speedup vs baseline: 1.7499x; 1.2087x over previous
#include <cuda_runtime.h>
#include <math.h>

#define BB 128
#define SS 256
#define HH 512

typedef unsigned long long u64;

// ---------------- device scratch (no allocations allowed) -------------------
__device__ float g_rsWr[HH];            // rowsum(Wr)
__device__ float g_rsW[HH];             // rowsum(W)
__device__ float g_part[4][BB * SS];    // per-jblock logit partials
__device__ float g_Gt[SS * BB];         // softmax gates, (s, b)
__device__ float g_C[2][HH * BB];       // recurrent state, transposed (h, b)
__device__ unsigned g_flagp[8][16][32]; // per-(bg,hg) step flag, 128B padded

// ---------------- helpers ------------------------------------------------------
__device__ __forceinline__ float tanh_approx(float x) {
    float y;
    asm("tanh.approx.f32 %0, %1;" : "=f"(y) : "f"(x));
    return y;
}
__device__ __forceinline__ float to_tf32(float x) {
    float y;
    asm("cvt.rna.tf32.f32 %0, %1;" : "=f"(y) : "f"(x));
    return y;
}
// pack two floats to bf16x2: lo -> low half, hi -> high half
__device__ __forceinline__ unsigned pkbf2(float lo, float hi) {
    unsigned r;
    asm("cvt.rn.bf16x2.f32 %0, %1, %2;" : "=r"(r) : "f"(hi), "f"(lo));
    return r;
}
__device__ __forceinline__ unsigned ld_acq(const unsigned* p) {
    unsigned v;
    asm volatile("ld.acquire.gpu.global.u32 %0, [%1];" : "=r"(v) : "l"(p));
    return v;
}
__device__ __forceinline__ void st_rel(unsigned* p, unsigned v) {
    asm volatile("st.release.gpu.global.u32 [%0], %1;" :: "l"(p), "r"(v) : "memory");
}
__device__ __forceinline__ void mma_bf16(float* d, const unsigned* a,
                                         unsigned b0, unsigned b1) {
    asm volatile(
        "mma.sync.aligned.m16n8k16.row.col.f32.bf16.bf16.f32 "
        "{%0,%1,%2,%3}, {%4,%5,%6,%7}, {%8,%9}, {%0,%1,%2,%3};"
        : "+f"(d[0]), "+f"(d[1]), "+f"(d[2]), "+f"(d[3])
        : "r"(a[0]), "r"(a[1]), "r"(a[2]), "r"(a[3]), "r"(b0), "r"(b1));
}
__device__ __forceinline__ void mma_tf32(float* d, const unsigned* a,
                                         unsigned b0, unsigned b1) {
    asm volatile(
        "mma.sync.aligned.m16n8k8.row.col.f32.tf32.tf32.f32 "
        "{%0,%1,%2,%3}, {%4,%5,%6,%7}, {%8,%9}, {%0,%1,%2,%3};"
        : "+f"(d[0]), "+f"(d[1]), "+f"(d[2]), "+f"(d[3])
        : "r"(a[0]), "r"(a[1]), "r"(a[2]), "r"(a[3]), "r"(b0), "r"(b1));
}

// ---------------- prep: rowsums of Wr and W ----------------------------------
__global__ void prep_kernel(const float* __restrict__ Wr, const float* __restrict__ W)
{
    int warp = threadIdx.x >> 5, lane = threadIdx.x & 31;
    int rowId = blockIdx.x * 8 + warp;               // 0..1023
    const float* src = (rowId < HH) ? Wr : W;
    int h = rowId & (HH - 1);
    const float4* s4 = reinterpret_cast<const float4*>(src + (size_t)h * HH);
    float s = 0.f;
    for (int i = lane; i < HH / 4; i += 32) {
        float4 v = s4[i];
        s += (v.x + v.y) + (v.z + v.w);
    }
#pragma unroll
    for (int o = 16; o > 0; o >>= 1) s += __shfl_xor_sync(0xffffffffu, s, o);
    if (lane == 0) {
        if (rowId < HH) g_rsWr[h] = s;
        else            g_rsW[h]  = s;
    }
}

// ---------------- gate MLP: bf16 mma.sync (m16n8k16) + fused z-build ----------
// grid (S/128, 512/128, B), 256 threads = 8 warps (4 s x 2 j). (R14 version.)
__global__ void __launch_bounds__(256, 2) gate_kernel(
    const float* __restrict__ facts, const float* __restrict__ q,
    const float* __restrict__ m, const float* __restrict__ z1w,
    const float* __restrict__ z1b, const float* __restrict__ z2w)
{
    extern __shared__ __align__(16) unsigned gsm_u[];
    unsigned* As32 = gsm_u;                 // [4][8][136] bf16x2 z-variants
    unsigned* Bs32 = As32 + 4 * 8 * 136;    // [4][8][136] bf16x2 z1w tile
    float* qs   = reinterpret_cast<float*>(Bs32 + 4 * 8 * 136);  // [512]
    float* ms   = qs + HH;                  // [512]
    float* z1bs = ms + HH;                  // [128]
    float* z2ws = z1bs + 128;               // [128]
    float* ps   = z2ws + 128;               // [8][32] per-warp s-partials

    int tid = threadIdx.x;
    int b  = blockIdx.z;
    int s0 = blockIdx.x * 128;
    int j0 = blockIdx.y * 128;
    int wid = tid >> 5, lane = tid & 31;
    int ws = wid >> 1, wj = wid & 1;      // warp grid 4(s) x 2(j)
    int gp = lane >> 2, tg = lane & 3;    // mma group / thread-in-group

    for (int i = tid; i < HH; i += 256) {
        qs[i] = q[b * HH + i];
        ms[i] = m[b * HH + i];
    }
    if (tid < 128) {
        z1bs[tid] = z1b[j0 + tid];
        z2ws[tid] = z2w[j0 + tid];
    }

    const float* fb = facts + ((size_t)b * SS + s0) * HH;

    float acc[2][8][4];                   // [s-subtile][j-subtile][frag]
#pragma unroll
    for (int i = 0; i < 2; i++)
#pragma unroll
        for (int j = 0; j < 8; j++)
#pragma unroll
            for (int k = 0; k < 4; k++) acc[i][j][k] = 0.f;

    for (int c = 0; c < 32; c++) {        // 32 chunks of 16 facts-k
        int k0 = c * 16;
        __syncthreads();                  // prev compute done (covers qs/ms @c=0)

        // build As32: 4 bf16x2 z-variants; idx -> (ss 0..127, kk2 0..7)
#pragma unroll
        for (int r = 0; r < 4; r++) {
            int idx = tid + r * 256;
            int ss = idx >> 3, kk2 = idx & 7;
            float2 fv = *reinterpret_cast<const float2*>(
                &fb[(size_t)ss * HH + k0 + 2 * kk2]);
            float2 qv = *reinterpret_cast<const float2*>(&qs[k0 + 2 * kk2]);
            float2 mv = *reinterpret_cast<const float2*>(&ms[k0 + 2 * kk2]);
            int base = kk2 * 136 + ss;
            As32[0 * 8 * 136 + base] = pkbf2(fv.x * qv.x, fv.y * qv.y);
            As32[1 * 8 * 136 + base] = pkbf2(fv.x * mv.x, fv.y * mv.y);
            As32[2 * 8 * 136 + base] = pkbf2(fabsf(fv.x - qv.x), fabsf(fv.y - qv.y));
            As32[3 * 8 * 136 + base] = pkbf2(fabsf(fv.x - mv.x), fabsf(fv.y - mv.y));
        }
        // stage Bs32: rows (v,kk2) pack z1w rows k0+2kk2 (lo) and +1 (hi)
#pragma unroll
        for (int r = 0; r < 4; r++) {
            int idx = tid + r * 256;        // 0..1023
            int row = idx >> 5;             // 0..31: v = row>>3, kk2 = row&7
            int jj4 = idx & 31;             // float4 col group
            size_t rA = (size_t)((row >> 3) * HH + k0 + 2 * (row & 7)) * HH + j0 + jj4 * 4;
            float4 a4 = *reinterpret_cast<const float4*>(&z1w[rA]);
            float4 b4 = *reinterpret_cast<const float4*>(&z1w[rA + HH]);
            unsigned* dst = &Bs32[row * 136 + jj4 * 4];
            dst[0] = pkbf2(a4.x, b4.x);
            dst[1] = pkbf2(a4.y, b4.y);
            dst[2] = pkbf2(a4.z, b4.z);
            dst[3] = pkbf2(a4.w, b4.w);
        }
        __syncthreads();                  // As/Bs ready

        // compute: 4 variants, one k16 mma-step each
#pragma unroll
        for (int v = 0; v < 4; v++) {
            const unsigned* Av = &As32[v * 8 * 136];
            const unsigned* Bv = &Bs32[v * 8 * 136];
            unsigned a[2][4];
#pragma unroll
            for (int st = 0; st < 2; st++) {
                int row0 = ws * 32 + st * 16 + gp;
                a[st][0] = Av[tg * 136 + row0];
                a[st][1] = Av[tg * 136 + row0 + 8];
                a[st][2] = Av[(tg + 4) * 136 + row0];
                a[st][3] = Av[(tg + 4) * 136 + row0 + 8];
            }
#pragma unroll
            for (int jt = 0; jt < 8; jt++) {
                int n0 = wj * 64 + jt * 8 + gp;
                unsigned b0 = Bv[tg * 136 + n0];
                unsigned b1 = Bv[(tg + 4) * 136 + n0];
                mma_bf16(acc[0][jt], a[0], b0, b1);
                mma_bf16(acc[1][jt], a[1], b0, b1);
            }
        }
    }

    // epilogue: tanh(acc + z1b) . z2w, reduce over this block's 128 j
#pragma unroll
    for (int st = 0; st < 2; st++) {
        float s_r0 = 0.f, s_r1 = 0.f;
#pragma unroll
        for (int jt = 0; jt < 8; jt++) {
#pragma unroll
            for (int ci = 0; ci < 2; ci++) {
                int col = wj * 64 + jt * 8 + tg * 2 + ci;
                float zb = z1bs[col], zw = z2ws[col];
                s_r0 = fmaf(tanh_approx(acc[st][jt][ci] + zb), zw, s_r0);
                s_r1 = fmaf(tanh_approx(acc[st][jt][2 + ci] + zb), zw, s_r1);
            }
        }
#pragma unroll
        for (int o = 1; o <= 2; o <<= 1) {
            s_r0 += __shfl_xor_sync(0xffffffffu, s_r0, o);
            s_r1 += __shfl_xor_sync(0xffffffffu, s_r1, o);
        }
        if (tg == 0) {
            ps[wid * 32 + st * 16 + gp]     = s_r0;
            ps[wid * 32 + st * 16 + 8 + gp] = s_r1;
        }
    }
    __syncthreads();
    if (tid < 128) {
        int wsx = tid >> 5, wi = tid & 31;
        float v = ps[(wsx * 2 + 0) * 32 + wi] + ps[(wsx * 2 + 1) * 32 + wi];
        g_part[blockIdx.y][b * SS + s0 + tid] = v;
    }
}

// ---------------- softmax over S per batch (also zeroes scan flags) -----------
__global__ void softmax_kernel()
{
    int b = blockIdx.x, s = threadIdx.x;   // 256 threads
    if (b == 0 && s < 128) g_flagp[s >> 4][s & 15][0] = 0u;  // zero flag words
    float l = 0.f;
#pragma unroll
    for (int jb = 0; jb < 4; jb++) l += g_part[jb][b * SS + s];
    __shared__ float sm[256];
    sm[s] = l;
    __syncthreads();
#pragma unroll
    for (int o = 128; o > 0; o >>= 1) {
        if (s < o) sm[s] = fmaxf(sm[s], sm[s + o]);
        __syncthreads();
    }
    float mx = sm[0];
    __syncthreads();
    float e = expf(l - mx);
    sm[s] = e;
    __syncthreads();
#pragma unroll
    for (int o = 128; o > 0; o >>= 1) {
        if (s < o) sm[s] += sm[s + o];
        __syncthreads();
    }
    g_Gt[s * BB + b] = e / sm[0];
}

// ---------------- persistent scan: tf32 tensor-core GEMM ----------------------
// 128 blocks = 16 hg x 8 bg, 512 threads = 16 warps = ks(4) x mt(4).
// D[64m(R|U)][16b] = Ws[64][512k] x C[512k][16b] via m16n8k8 tf32 mma.
// Weight fragments live in registers (constant across all steps). Warp (ks,mt)
// stages C k-slab [wid*32, +32) (producer hg = wid -> per-warp dataflow poll).
__global__ void __launch_bounds__(512, 1) scan_persist(
    const float* __restrict__ facts,
    const float* __restrict__ Ur, const float* __restrict__ U,
    const float* __restrict__ br, const float* __restrict__ bur,
    const float* __restrict__ bw, const float* __restrict__ bu)
{
    extern __shared__ __align__(16) float dsmf[];
    float* Ws  = dsmf;                     // [512][64] tf32 weights (k-major)
    float* Cs  = Ws + 512 * 64;            // [512][24] tf32 C (pad 24)
    float* red = Cs + 512 * 24;            // [4][64][17] k-split partials

    __shared__ float hcs[5][32];

    int tid = threadIdx.x;
    int hg = blockIdx.x >> 3;      // 0..15
    int bg = blockIdx.x & 7;       // 0..7
    int h0 = hg * 32;
    int b0 = bg * 16;

    // one-time: build tf32 weight slab Wm[m][k]: m<32 -> Ur[:,h0+m], else U
    for (int idx = tid; idx < 512 * 64; idx += 512) {
        int k = idx >> 6, mm = idx & 63;
        float w = (mm < 32) ? Ur[(size_t)k * HH + h0 + mm]
                            : U[(size_t)k * HH + h0 + mm - 32];
        Ws[idx] = to_tf32(w);
    }
    if (tid < 32) {
        int h = h0 + tid;
        hcs[0][tid] = g_rsWr[h];
        hcs[1][tid] = br[h] + bur[h];
        hcs[2][tid] = g_rsW[h];
        hcs[3][tid] = bw[h];
        hcs[4][tid] = bu[h];
    }
    __syncthreads();

    int wid = tid >> 5, lane = tid & 31;
    int ks = wid >> 2, mt = wid & 3;
    int gp = lane >> 2, tg = lane & 3;

    // A fragments in registers: 16 ksteps x 4 regs, constant across steps
    unsigned areg[16][4];
#pragma unroll
    for (int i = 0; i < 16; i++) {
        int k = ks * 128 + i * 8;
        int m0 = mt * 16 + gp;
        areg[i][0] = __float_as_uint(Ws[(k + tg) * 64 + m0]);
        areg[i][1] = __float_as_uint(Ws[(k + tg) * 64 + m0 + 8]);
        areg[i][2] = __float_as_uint(Ws[(k + tg + 4) * 64 + m0]);
        areg[i][3] = __float_as_uint(Ws[(k + tg + 4) * 64 + m0 + 8]);
    }

    // epilogue mapping: hl fastest -> coalesced facts
    int hl = tid & 31, bl = tid >> 5;
    int eh = h0 + hl, eb = b0 + bl;
    float cur_c = 0.f;

    unsigned* myflag = &g_flagp[bg][hg][0];
    const unsigned* srcflag = &g_flagp[bg][wid][0];  // producer of my staged slab

    for (int s = 0; s < SS; s++) {
        float aR = 0.f, aU = 0.f;

        if (s > 0) {
            // per-warp poll: producer of my staging slab (hg = wid)
            if (lane == 0) {
                while (ld_acq(srcflag) < (unsigned)s) {}
            }
            __syncwarp();

            // stage my 32-k slab of C as tf32 (STS.128-aligned, pad 24)
            const float* __restrict__ Cin = g_C[s & 1];
            {
                int kb = wid * 32;
#pragma unroll
                for (int c = 0; c < 4; c++) {
                    int chunk = lane + c * 32;
                    int kk = kb + (chunk >> 2);
                    int qd = chunk & 3;
                    float4 v = __ldcg(reinterpret_cast<const float4*>(
                        Cin + (size_t)kk * BB + b0) + qd);
                    float4 t;
                    t.x = to_tf32(v.x); t.y = to_tf32(v.y);
                    t.z = to_tf32(v.z); t.w = to_tf32(v.w);
                    *reinterpret_cast<float4*>(&Cs[kk * 24 + qd * 4]) = t;
                }
            }
            __syncthreads();   // all slabs staged

            // GEMM: 16 ksteps, A from regs, B frags from Cs
            float acc0[4] = {0.f, 0.f, 0.f, 0.f};
            float acc1[4] = {0.f, 0.f, 0.f, 0.f};
            int kbase = ks * 128;
#pragma unroll
            for (int i = 0; i < 16; i++) {
                int k = kbase + i * 8;
                unsigned b00 = __float_as_uint(Cs[(k + tg) * 24 + gp]);
                unsigned b01 = __float_as_uint(Cs[(k + tg + 4) * 24 + gp]);
                unsigned b10 = __float_as_uint(Cs[(k + tg) * 24 + 8 + gp]);
                unsigned b11 = __float_as_uint(Cs[(k + tg + 4) * 24 + 8 + gp]);
                mma_tf32(acc0, areg[i], b00, b01);
                mma_tf32(acc1, areg[i], b10, b11);
            }

            // write k-split partials: D[m][n], d0=[gp][tg*2] d1=+1 d2=[gp+8][tg*2] d3=+1
            {
                float* rp = &red[(size_t)ks * 64 * 17];
                int mrow = mt * 16 + gp;
                rp[mrow * 17 + tg * 2]           = acc0[0];
                rp[mrow * 17 + tg * 2 + 1]       = acc0[1];
                rp[(mrow + 8) * 17 + tg * 2]     = acc0[2];
                rp[(mrow + 8) * 17 + tg * 2 + 1] = acc0[3];
                rp[mrow * 17 + 8 + tg * 2]           = acc1[0];
                rp[mrow * 17 + 8 + tg * 2 + 1]       = acc1[1];
                rp[(mrow + 8) * 17 + 8 + tg * 2]     = acc1[2];
                rp[(mrow + 8) * 17 + 8 + tg * 2 + 1] = acc1[3];
            }
            __syncthreads();

            // 4-way reduce for my (h,b): m=hl -> aR, m=32+hl -> aU
#pragma unroll
            for (int t = 0; t < 4; t++) {
                aR += red[(size_t)t * 64 * 17 + hl * 17 + bl];
                aU += red[(size_t)t * 64 * 17 + (32 + hl) * 17 + bl];
            }
        }

        // fused epilogue: nonlinearity + blend; C kept in a register
        {
            float* __restrict__ Cout = g_C[(s + 1) & 1];
            float fv = __ldg(facts + ((size_t)eb * SS + s) * HH + eh);
            float g = g_Gt[s * BB + eb];
            float rr = 1.f / (1.f + expf(-(fmaf(fv, hcs[0][hl], hcs[1][hl]) + aR)));
            float ht = tanhf(fmaf(rr, aU + hcs[4][hl],
                                  fmaf(fv, hcs[2][hl], hcs[3][hl])));
            cur_c = fmaf(g, ht - cur_c, cur_c);
            __stcg(&Cout[(size_t)eh * BB + eb], cur_c);
        }
        __syncthreads();       // all C stores issued; also seals red reads
        if (tid == 0) st_rel(myflag, (unsigned)(s + 1));
    }
}

// ---------------- final: relu(concat @ nm_w + nm_b) ---------------------------
__global__ void __launch_bounds__(512) final_kernel(
    const float* __restrict__ prevM, const float* __restrict__ q,
    const float* __restrict__ nm_w, const float* __restrict__ nm_b,
    float* __restrict__ out)
{
    __shared__ float cs[3 * HH];
    int b = blockIdx.x, tid = threadIdx.x;    // 512 threads
    cs[tid]          = prevM[b * HH + tid];
    cs[HH + tid]     = g_C[0][(size_t)tid * BB + b];   // final C lives in buffer 0
    cs[2 * HH + tid] = q[b * HH + tid];
    __syncthreads();
    float acc = nm_b[tid];
#pragma unroll 8
    for (int k = 0; k < 3 * HH; k++)
        acc = fmaf(cs[k], nm_w[(size_t)k * HH + tid], acc);
    out[b * HH + tid] = fmaxf(acc, 0.f);
}

// ---------------- launch -------------------------------------------------------
extern "C" void kernel_launch(void* const* d_in, const int* in_sizes, int n_in,
                              void* d_out, int out_size)
{
    const float* facts     = (const float*)d_in[0];
    const float* questions = (const float*)d_in[1];
    const float* prevM     = (const float*)d_in[2];
    const float* z1_w      = (const float*)d_in[3];
    const float* z1_b      = (const float*)d_in[4];
    const float* z2_w      = (const float*)d_in[5];
    // d_in[6] z2_b: constant shift, softmax-invariant — unused
    const float* Wr        = (const float*)d_in[7];
    const float* br        = (const float*)d_in[8];
    const float* Ur        = (const float*)d_in[9];
    const float* bur       = (const float*)d_in[10];
    const float* W         = (const float*)d_in[11];
    const float* bw        = (const float*)d_in[12];
    const float* U         = (const float*)d_in[13];
    const float* bu        = (const float*)d_in[14];
    const float* nm_w      = (const float*)d_in[15];
    const float* nm_b      = (const float*)d_in[16];
    float* out = (float*)d_out;

    const int scan_smem = (512 * 64 + 512 * 24 + 4 * 64 * 17) * 4;  // 197632
    cudaFuncSetAttribute(scan_persist,
                         cudaFuncAttributeMaxDynamicSharedMemorySize, scan_smem);
    const int gate_smem = (2 * 4 * 8 * 136 + 2 * HH + 2 * 128 + 256) * 4; // 40960
    cudaFuncSetAttribute(gate_kernel,
                         cudaFuncAttributeMaxDynamicSharedMemorySize, gate_smem);

    prep_kernel<<<128, 256>>>(Wr, W);
    gate_kernel<<<dim3(2, 4, BB), 256, gate_smem>>>(facts, questions, prevM,
                                                    z1_w, z1_b, z2_w);
    softmax_kernel<<<BB, 256>>>();
    scan_persist<<<128, 512, scan_smem>>>(facts, Ur, U, br, bur, bw, bu);
    final_kernel<<<BB, 512>>>(prevM, questions, nm_w, nm_b, out);
}

// round 17
// speedup vs baseline: 2.0496x; 1.1713x over previous
#include <cuda_runtime.h>
#include <math.h>

#define BB 128
#define SS 256
#define HH 512

typedef unsigned long long u64;

// ---------------- device scratch (no allocations allowed) -------------------
__device__ float g_rsWr[HH];            // rowsum(Wr)
__device__ float g_rsW[HH];             // rowsum(W)
__device__ float g_part[4][BB * SS];    // per-jblock logit partials
__device__ float g_Gt[SS * BB];         // softmax gates, (s, b)
__device__ float g_C[2][HH * BB];       // recurrent state, transposed (h, b)
__device__ unsigned g_flagp[8][16][32]; // per-(bg,hg) step flag, 128B padded

// ---------------- helpers ------------------------------------------------------
__device__ __forceinline__ float tanh_approx(float x) {
    float y;
    asm("tanh.approx.f32 %0, %1;" : "=f"(y) : "f"(x));
    return y;
}
__device__ __forceinline__ float to_tf32(float x) {
    float y;
    asm("cvt.rna.tf32.f32 %0, %1;" : "=f"(y) : "f"(x));
    return y;
}
// pack two floats to bf16x2: lo -> low half, hi -> high half
__device__ __forceinline__ unsigned pkbf2(float lo, float hi) {
    unsigned r;
    asm("cvt.rn.bf16x2.f32 %0, %1, %2;" : "=r"(r) : "f"(hi), "f"(lo));
    return r;
}
__device__ __forceinline__ unsigned ld_acq(const unsigned* p) {
    unsigned v;
    asm volatile("ld.acquire.gpu.global.u32 %0, [%1];" : "=r"(v) : "l"(p));
    return v;
}
__device__ __forceinline__ void st_rel(unsigned* p, unsigned v) {
    asm volatile("st.release.gpu.global.u32 [%0], %1;" :: "l"(p), "r"(v) : "memory");
}
__device__ __forceinline__ void mma_bf16(float* d, const unsigned* a,
                                         unsigned b0, unsigned b1) {
    asm volatile(
        "mma.sync.aligned.m16n8k16.row.col.f32.bf16.bf16.f32 "
        "{%0,%1,%2,%3}, {%4,%5,%6,%7}, {%8,%9}, {%0,%1,%2,%3};"
        : "+f"(d[0]), "+f"(d[1]), "+f"(d[2]), "+f"(d[3])
        : "r"(a[0]), "r"(a[1]), "r"(a[2]), "r"(a[3]), "r"(b0), "r"(b1));
}
__device__ __forceinline__ void mma_tf32(float* d, const unsigned* a,
                                         unsigned b0, unsigned b1) {
    asm volatile(
        "mma.sync.aligned.m16n8k8.row.col.f32.tf32.tf32.f32 "
        "{%0,%1,%2,%3}, {%4,%5,%6,%7}, {%8,%9}, {%0,%1,%2,%3};"
        : "+f"(d[0]), "+f"(d[1]), "+f"(d[2]), "+f"(d[3])
        : "r"(a[0]), "r"(a[1]), "r"(a[2]), "r"(a[3]), "r"(b0), "r"(b1));
}

// ---------------- prep: rowsums of Wr and W ----------------------------------
__global__ void prep_kernel(const float* __restrict__ Wr, const float* __restrict__ W)
{
    int warp = threadIdx.x >> 5, lane = threadIdx.x & 31;
    int rowId = blockIdx.x * 8 + warp;               // 0..1023
    const float* src = (rowId < HH) ? Wr : W;
    int h = rowId & (HH - 1);
    const float4* s4 = reinterpret_cast<const float4*>(src + (size_t)h * HH);
    float s = 0.f;
    for (int i = lane; i < HH / 4; i += 32) {
        float4 v = s4[i];
        s += (v.x + v.y) + (v.z + v.w);
    }
#pragma unroll
    for (int o = 16; o > 0; o >>= 1) s += __shfl_xor_sync(0xffffffffu, s, o);
    if (lane == 0) {
        if (rowId < HH) g_rsWr[h] = s;
        else            g_rsW[h]  = s;
    }
}

// ---------------- gate MLP: bf16 mma.sync (m16n8k16) + fused z-build ----------
// grid (S/128, 512/128, B), 256 threads = 8 warps (4 s x 2 j). (R14 version.)
__global__ void __launch_bounds__(256, 2) gate_kernel(
    const float* __restrict__ facts, const float* __restrict__ q,
    const float* __restrict__ m, const float* __restrict__ z1w,
    const float* __restrict__ z1b, const float* __restrict__ z2w)
{
    extern __shared__ __align__(16) unsigned gsm_u[];
    unsigned* As32 = gsm_u;                 // [4][8][136] bf16x2 z-variants
    unsigned* Bs32 = As32 + 4 * 8 * 136;    // [4][8][136] bf16x2 z1w tile
    float* qs   = reinterpret_cast<float*>(Bs32 + 4 * 8 * 136);  // [512]
    float* ms   = qs + HH;                  // [512]
    float* z1bs = ms + HH;                  // [128]
    float* z2ws = z1bs + 128;               // [128]
    float* ps   = z2ws + 128;               // [8][32] per-warp s-partials

    int tid = threadIdx.x;
    int b  = blockIdx.z;
    int s0 = blockIdx.x * 128;
    int j0 = blockIdx.y * 128;
    int wid = tid >> 5, lane = tid & 31;
    int ws = wid >> 1, wj = wid & 1;      // warp grid 4(s) x 2(j)
    int gp = lane >> 2, tg = lane & 3;    // mma group / thread-in-group

    for (int i = tid; i < HH; i += 256) {
        qs[i] = q[b * HH + i];
        ms[i] = m[b * HH + i];
    }
    if (tid < 128) {
        z1bs[tid] = z1b[j0 + tid];
        z2ws[tid] = z2w[j0 + tid];
    }

    const float* fb = facts + ((size_t)b * SS + s0) * HH;

    float acc[2][8][4];                   // [s-subtile][j-subtile][frag]
#pragma unroll
    for (int i = 0; i < 2; i++)
#pragma unroll
        for (int j = 0; j < 8; j++)
#pragma unroll
            for (int k = 0; k < 4; k++) acc[i][j][k] = 0.f;

    for (int c = 0; c < 32; c++) {        // 32 chunks of 16 facts-k
        int k0 = c * 16;
        __syncthreads();                  // prev compute done (covers qs/ms @c=0)

        // build As32: 4 bf16x2 z-variants; idx -> (ss 0..127, kk2 0..7)
#pragma unroll
        for (int r = 0; r < 4; r++) {
            int idx = tid + r * 256;
            int ss = idx >> 3, kk2 = idx & 7;
            float2 fv = *reinterpret_cast<const float2*>(
                &fb[(size_t)ss * HH + k0 + 2 * kk2]);
            float2 qv = *reinterpret_cast<const float2*>(&qs[k0 + 2 * kk2]);
            float2 mv = *reinterpret_cast<const float2*>(&ms[k0 + 2 * kk2]);
            int base = kk2 * 136 + ss;
            As32[0 * 8 * 136 + base] = pkbf2(fv.x * qv.x, fv.y * qv.y);
            As32[1 * 8 * 136 + base] = pkbf2(fv.x * mv.x, fv.y * mv.y);
            As32[2 * 8 * 136 + base] = pkbf2(fabsf(fv.x - qv.x), fabsf(fv.y - qv.y));
            As32[3 * 8 * 136 + base] = pkbf2(fabsf(fv.x - mv.x), fabsf(fv.y - mv.y));
        }
        // stage Bs32: rows (v,kk2) pack z1w rows k0+2kk2 (lo) and +1 (hi)
#pragma unroll
        for (int r = 0; r < 4; r++) {
            int idx = tid + r * 256;        // 0..1023
            int row = idx >> 5;             // 0..31: v = row>>3, kk2 = row&7
            int jj4 = idx & 31;             // float4 col group
            size_t rA = (size_t)((row >> 3) * HH + k0 + 2 * (row & 7)) * HH + j0 + jj4 * 4;
            float4 a4 = *reinterpret_cast<const float4*>(&z1w[rA]);
            float4 b4 = *reinterpret_cast<const float4*>(&z1w[rA + HH]);
            unsigned* dst = &Bs32[row * 136 + jj4 * 4];
            dst[0] = pkbf2(a4.x, b4.x);
            dst[1] = pkbf2(a4.y, b4.y);
            dst[2] = pkbf2(a4.z, b4.z);
            dst[3] = pkbf2(a4.w, b4.w);
        }
        __syncthreads();                  // As/Bs ready

        // compute: 4 variants, one k16 mma-step each
#pragma unroll
        for (int v = 0; v < 4; v++) {
            const unsigned* Av = &As32[v * 8 * 136];
            const unsigned* Bv = &Bs32[v * 8 * 136];
            unsigned a[2][4];
#pragma unroll
            for (int st = 0; st < 2; st++) {
                int row0 = ws * 32 + st * 16 + gp;
                a[st][0] = Av[tg * 136 + row0];
                a[st][1] = Av[tg * 136 + row0 + 8];
                a[st][2] = Av[(tg + 4) * 136 + row0];
                a[st][3] = Av[(tg + 4) * 136 + row0 + 8];
            }
#pragma unroll
            for (int jt = 0; jt < 8; jt++) {
                int n0 = wj * 64 + jt * 8 + gp;
                unsigned b0 = Bv[tg * 136 + n0];
                unsigned b1 = Bv[(tg + 4) * 136 + n0];
                mma_bf16(acc[0][jt], a[0], b0, b1);
                mma_bf16(acc[1][jt], a[1], b0, b1);
            }
        }
    }

    // epilogue: tanh(acc + z1b) . z2w, reduce over this block's 128 j
#pragma unroll
    for (int st = 0; st < 2; st++) {
        float s_r0 = 0.f, s_r1 = 0.f;
#pragma unroll
        for (int jt = 0; jt < 8; jt++) {
#pragma unroll
            for (int ci = 0; ci < 2; ci++) {
                int col = wj * 64 + jt * 8 + tg * 2 + ci;
                float zb = z1bs[col], zw = z2ws[col];
                s_r0 = fmaf(tanh_approx(acc[st][jt][ci] + zb), zw, s_r0);
                s_r1 = fmaf(tanh_approx(acc[st][jt][2 + ci] + zb), zw, s_r1);
            }
        }
#pragma unroll
        for (int o = 1; o <= 2; o <<= 1) {
            s_r0 += __shfl_xor_sync(0xffffffffu, s_r0, o);
            s_r1 += __shfl_xor_sync(0xffffffffu, s_r1, o);
        }
        if (tg == 0) {
            ps[wid * 32 + st * 16 + gp]     = s_r0;
            ps[wid * 32 + st * 16 + 8 + gp] = s_r1;
        }
    }
    __syncthreads();
    if (tid < 128) {
        int wsx = tid >> 5, wi = tid & 31;
        float v = ps[(wsx * 2 + 0) * 32 + wi] + ps[(wsx * 2 + 1) * 32 + wi];
        g_part[blockIdx.y][b * SS + s0 + tid] = v;
    }
}

// ---------------- softmax over S per batch (also zeroes scan flags) -----------
__global__ void softmax_kernel()
{
    int b = blockIdx.x, s = threadIdx.x;   // 256 threads
    if (b == 0 && s < 128) g_flagp[s >> 4][s & 15][0] = 0u;  // zero flag words
    float l = 0.f;
#pragma unroll
    for (int jb = 0; jb < 4; jb++) l += g_part[jb][b * SS + s];
    __shared__ float sm[256];
    sm[s] = l;
    __syncthreads();
#pragma unroll
    for (int o = 128; o > 0; o >>= 1) {
        if (s < o) sm[s] = fmaxf(sm[s], sm[s + o]);
        __syncthreads();
    }
    float mx = sm[0];
    __syncthreads();
    float e = expf(l - mx);
    sm[s] = e;
    __syncthreads();
#pragma unroll
    for (int o = 128; o > 0; o >>= 1) {
        if (s < o) sm[s] += sm[s + o];
        __syncthreads();
    }
    g_Gt[s * BB + b] = e / sm[0];
}

// ---------------- persistent scan: tf32 tensor-core GEMM ----------------------
// 128 blocks = 16 hg x 8 bg, 512 threads = 16 warps = ks(4) x mt(4).
// D[64m(R|U)][16b] = Ws[64][512k] x C[512k][16b] via m16n8k8 tf32 mma.
// Weight fragments in registers; warp (ks,mt) stages C k-slab [wid*32, +32)
// (producer hg = wid -> per-warp dataflow poll). Epilogue inputs (facts, G)
// hoisted before the poll; fast-math sigmoid/tanh on the post-reduce path.
__global__ void __launch_bounds__(512, 1) scan_persist(
    const float* __restrict__ facts,
    const float* __restrict__ Ur, const float* __restrict__ U,
    const float* __restrict__ br, const float* __restrict__ bur,
    const float* __restrict__ bw, const float* __restrict__ bu)
{
    extern __shared__ __align__(16) float dsmf[];
    float* Ws  = dsmf;                     // [512][64] tf32 weights (k-major)
    float* Cs  = Ws + 512 * 64;            // [512][24] tf32 C (pad 24)
    float* red = Cs + 512 * 24;            // [4][64][17] k-split partials

    __shared__ float hcs[5][32];

    int tid = threadIdx.x;
    int hg = blockIdx.x >> 3;      // 0..15
    int bg = blockIdx.x & 7;       // 0..7
    int h0 = hg * 32;
    int b0 = bg * 16;

    // one-time: build tf32 weight slab Wm[m][k]: m<32 -> Ur[:,h0+m], else U
    for (int idx = tid; idx < 512 * 64; idx += 512) {
        int k = idx >> 6, mm = idx & 63;
        float w = (mm < 32) ? Ur[(size_t)k * HH + h0 + mm]
                            : U[(size_t)k * HH + h0 + mm - 32];
        Ws[idx] = to_tf32(w);
    }
    if (tid < 32) {
        int h = h0 + tid;
        hcs[0][tid] = g_rsWr[h];
        hcs[1][tid] = br[h] + bur[h];
        hcs[2][tid] = g_rsW[h];
        hcs[3][tid] = bw[h];
        hcs[4][tid] = bu[h];
    }
    __syncthreads();

    int wid = tid >> 5, lane = tid & 31;
    int ks = wid >> 2, mt = wid & 3;
    int gp = lane >> 2, tg = lane & 3;

    // A fragments in registers: 16 ksteps x 4 regs, constant across steps
    unsigned areg[16][4];
#pragma unroll
    for (int i = 0; i < 16; i++) {
        int k = ks * 128 + i * 8;
        int m0 = mt * 16 + gp;
        areg[i][0] = __float_as_uint(Ws[(k + tg) * 64 + m0]);
        areg[i][1] = __float_as_uint(Ws[(k + tg) * 64 + m0 + 8]);
        areg[i][2] = __float_as_uint(Ws[(k + tg + 4) * 64 + m0]);
        areg[i][3] = __float_as_uint(Ws[(k + tg + 4) * 64 + m0 + 8]);
    }

    // epilogue mapping: hl fastest -> coalesced facts
    int hl = tid & 31, bl = tid >> 5;
    int eh = h0 + hl, eb = b0 + bl;
    float cur_c = 0.f;

    unsigned* myflag = &g_flagp[bg][hg][0];
    const unsigned* srcflag = &g_flagp[bg][wid][0];  // producer of my staged slab

    for (int s = 0; s < SS; s++) {
        // hoisted epilogue inputs: depend only on s; latency hidden under
        // poll + stage + GEMM instead of sitting on the post-reduce chain.
        float fv = __ldg(facts + ((size_t)eb * SS + s) * HH + eh);
        float gt = __ldg(g_Gt + s * BB + eb);

        float aR = 0.f, aU = 0.f;

        if (s > 0) {
            // per-warp poll: producer of my staging slab (hg = wid)
            if (lane == 0) {
                while (ld_acq(srcflag) < (unsigned)s) {}
            }
            __syncwarp();

            // stage my 32-k slab of C as tf32 (STS.128-aligned, pad 24)
            const float* __restrict__ Cin = g_C[s & 1];
            {
                int kb = wid * 32;
#pragma unroll
                for (int c = 0; c < 4; c++) {
                    int chunk = lane + c * 32;
                    int kk = kb + (chunk >> 2);
                    int qd = chunk & 3;
                    float4 v = __ldcg(reinterpret_cast<const float4*>(
                        Cin + (size_t)kk * BB + b0) + qd);
                    float4 t;
                    t.x = to_tf32(v.x); t.y = to_tf32(v.y);
                    t.z = to_tf32(v.z); t.w = to_tf32(v.w);
                    *reinterpret_cast<float4*>(&Cs[kk * 24 + qd * 4]) = t;
                }
            }
            __syncthreads();   // all slabs staged

            // GEMM: 16 ksteps, A from regs, B frags from Cs
            float acc0[4] = {0.f, 0.f, 0.f, 0.f};
            float acc1[4] = {0.f, 0.f, 0.f, 0.f};
            int kbase = ks * 128;
#pragma unroll
            for (int i = 0; i < 16; i++) {
                int k = kbase + i * 8;
                unsigned b00 = __float_as_uint(Cs[(k + tg) * 24 + gp]);
                unsigned b01 = __float_as_uint(Cs[(k + tg + 4) * 24 + gp]);
                unsigned b10 = __float_as_uint(Cs[(k + tg) * 24 + 8 + gp]);
                unsigned b11 = __float_as_uint(Cs[(k + tg + 4) * 24 + 8 + gp]);
                mma_tf32(acc0, areg[i], b00, b01);
                mma_tf32(acc1, areg[i], b10, b11);
            }

            // write k-split partials: D[m][n], d0=[gp][tg*2] d1=+1 d2=[gp+8][tg*2] d3=+1
            {
                float* rp = &red[(size_t)ks * 64 * 17];
                int mrow = mt * 16 + gp;
                rp[mrow * 17 + tg * 2]           = acc0[0];
                rp[mrow * 17 + tg * 2 + 1]       = acc0[1];
                rp[(mrow + 8) * 17 + tg * 2]     = acc0[2];
                rp[(mrow + 8) * 17 + tg * 2 + 1] = acc0[3];
                rp[mrow * 17 + 8 + tg * 2]           = acc1[0];
                rp[mrow * 17 + 8 + tg * 2 + 1]       = acc1[1];
                rp[(mrow + 8) * 17 + 8 + tg * 2]     = acc1[2];
                rp[(mrow + 8) * 17 + 8 + tg * 2 + 1] = acc1[3];
            }
            __syncthreads();

            // 4-way reduce for my (h,b): m=hl -> aR, m=32+hl -> aU
#pragma unroll
            for (int t = 0; t < 4; t++) {
                aR += red[(size_t)t * 64 * 17 + hl * 17 + bl];
                aU += red[(size_t)t * 64 * 17 + (32 + hl) * 17 + bl];
            }
        }

        // fused epilogue: fast-math nonlinearity + blend; C kept in a register
        {
            float* __restrict__ Cout = g_C[(s + 1) & 1];
            float xR = fmaf(fv, hcs[0][hl], hcs[1][hl]) + aR;
            float rr = __fdividef(1.f, 1.f + __expf(-xR));
            float xH = fmaf(rr, aU + hcs[4][hl],
                            fmaf(fv, hcs[2][hl], hcs[3][hl]));
            float e2 = __expf(-2.f * fabsf(xH));
            float ht = copysignf(__fdividef(1.f - e2, 1.f + e2), xH);
            cur_c = fmaf(gt, ht - cur_c, cur_c);
            __stcg(&Cout[(size_t)eh * BB + eb], cur_c);
        }
        __syncthreads();       // all C stores issued; also seals red reads
        if (tid == 0) st_rel(myflag, (unsigned)(s + 1));
    }
}

// ---------------- final: relu(concat @ nm_w + nm_b) ---------------------------
__global__ void __launch_bounds__(512) final_kernel(
    const float* __restrict__ prevM, const float* __restrict__ q,
    const float* __restrict__ nm_w, const float* __restrict__ nm_b,
    float* __restrict__ out)
{
    __shared__ float cs[3 * HH];
    int b = blockIdx.x, tid = threadIdx.x;    // 512 threads
    cs[tid]          = prevM[b * HH + tid];
    cs[HH + tid]     = g_C[0][(size_t)tid * BB + b];   // final C lives in buffer 0
    cs[2 * HH + tid] = q[b * HH + tid];
    __syncthreads();
    float acc = nm_b[tid];
#pragma unroll 8
    for (int k = 0; k < 3 * HH; k++)
        acc = fmaf(cs[k], nm_w[(size_t)k * HH + tid], acc);
    out[b * HH + tid] = fmaxf(acc, 0.f);
}

// ---------------- launch -------------------------------------------------------
extern "C" void kernel_launch(void* const* d_in, const int* in_sizes, int n_in,
                              void* d_out, int out_size)
{
    const float* facts     = (const float*)d_in[0];
    const float* questions = (const float*)d_in[1];
    const float* prevM     = (const float*)d_in[2];
    const float* z1_w      = (const float*)d_in[3];
    const float* z1_b      = (const float*)d_in[4];
    const float* z2_w      = (const float*)d_in[5];
    // d_in[6] z2_b: constant shift, softmax-invariant — unused
    const float* Wr        = (const float*)d_in[7];
    const float* br        = (const float*)d_in[8];
    const float* Ur        = (const float*)d_in[9];
    const float* bur       = (const float*)d_in[10];
    const float* W         = (const float*)d_in[11];
    const float* bw        = (const float*)d_in[12];
    const float* U         = (const float*)d_in[13];
    const float* bu        = (const float*)d_in[14];
    const float* nm_w      = (const float*)d_in[15];
    const float* nm_b      = (const float*)d_in[16];
    float* out = (float*)d_out;

    const int scan_smem = (512 * 64 + 512 * 24 + 4 * 64 * 17) * 4;  // 197632
    cudaFuncSetAttribute(scan_persist,
                         cudaFuncAttributeMaxDynamicSharedMemorySize, scan_smem);
    const int gate_smem = (2 * 4 * 8 * 136 + 2 * HH + 2 * 128 + 256) * 4; // 40960
    cudaFuncSetAttribute(gate_kernel,
                         cudaFuncAttributeMaxDynamicSharedMemorySize, gate_smem);

    prep_kernel<<<128, 256>>>(Wr, W);
    gate_kernel<<<dim3(2, 4, BB), 256, gate_smem>>>(facts, questions, prevM,
                                                    z1_w, z1_b, z2_w);
    softmax_kernel<<<BB, 256>>>();
    scan_persist<<<128, 512, scan_smem>>>(facts, Ur, U, br, bur, bw, bu);
    final_kernel<<<BB, 512>>>(prevM, questions, nm_w, nm_b, out);
}